// round 11
// baseline (speedup 1.0000x reference)
#include <cuda_runtime.h>
#include <cstdint>

#define NN 50000
#define NE 600000
#define DD 128
#define NL 4
#define NG 512
#define NC 10
#define AST 132        // padded smem stride (floats)
#define MT 64          // GEMM M tile
#define NTILES ((NN + MT - 1) / MT)   // 782

// ---- scratch (device globals: allocation-free) ----
__device__ float g_H[NN * DD];
__device__ float g_Z[NN * DD];
__device__ float g_T[NN * DD];
__device__ float g_sum[NL * DD];
__device__ float g_sqs[NL * DD];
__device__ float g_pool[NG * NL * DD];
__device__ uint32_t g_Wt[2][NL][DD * AST];   // transposed, padded, tf32-converted

__device__ int g_src[NE];
__device__ int g_dst[NE];
__device__ int g_batch[NN];
__device__ int g_deg[NN];
__device__ int g_ptr[NN + 1];
__device__ int g_off[NN];
__device__ int g_csr_src[NE];
__device__ int g_mode_ei;
__device__ int g_mode_b;
__device__ int g_scan_done;

__device__ __forceinline__ void red_add_v4(float* p, float4 v) {
    asm volatile("red.global.add.v4.f32 [%0], {%1, %2, %3, %4};"
                 :: "l"(p), "f"(v.x), "f"(v.y), "f"(v.z), "f"(v.w)
                 : "memory");
}
__device__ __forceinline__ uint32_t f2tf32(float f) {
    uint32_t u;
    asm("cvt.rna.tf32.f32 %0, %1;" : "=r"(u) : "f"(f));
    return u;
}
__device__ __forceinline__ void mma_tf32(float& c0, float& c1, float& c2, float& c3,
                                         uint32_t a0, uint32_t a1, uint32_t a2, uint32_t a3,
                                         uint32_t b0, uint32_t b1) {
    asm volatile(
        "mma.sync.aligned.m16n8k8.row.col.f32.tf32.tf32.f32 "
        "{%0,%1,%2,%3}, {%4,%5,%6,%7}, {%8,%9}, {%0,%1,%2,%3};"
        : "+f"(c0), "+f"(c1), "+f"(c2), "+f"(c3)
        : "r"(a0), "r"(a1), "r"(a2), "r"(a3), "r"(b0), "r"(b1));
}

// ---------------- preamble ----------------
__global__ void detect_kernel(const int* __restrict__ ei32,
                              const int* __restrict__ b32) {
    int i = blockIdx.x * blockDim.x + threadIdx.x;
    int idx = 2 * i + 1;
    if (idx < 2 * NE) { if (ei32[idx] != 0) atomicExch(&g_mode_ei, 0); }
    if (idx < NN)     { if (b32[idx]  != 0) atomicExch(&g_mode_b, 0); }
}

__global__ void convert_hist_kernel(const int* __restrict__ ei32,
                                    const int* __restrict__ b32) {
    int i = blockIdx.x * blockDim.x + threadIdx.x;
    int m_ei = g_mode_ei, m_b = g_mode_b;
    if (i < NE) {
        int s = m_ei ? ei32[2 * i]        : ei32[i];
        int d = m_ei ? ei32[2 * (NE + i)] : ei32[NE + i];
        g_src[i] = s;
        g_dst[i] = d;
        atomicAdd(&g_deg[d], 1);
    }
    if (i < NN) g_batch[i] = m_b ? b32[2 * i] : b32[i];
}

// persistent, all-resident (148 CTAs x 256 thr):
// block 0: exclusive degree scan -> g_ptr/g_off; blocks 1..147: weight prep.
// then flag-sync, then all blocks scatter edges into CSR.
__global__ __launch_bounds__(256)
void scan_wprep_scatter_kernel(const float* __restrict__ W1,
                               const float* __restrict__ W2) {
    int tid = threadIdx.x;
    if (blockIdx.x == 0) {
        __shared__ int sh[256];
        const int CH = (NN + 255) / 256;   // 196
        int b0 = tid * CH, b1 = min(b0 + CH, NN);
        int s = 0;
        for (int i = b0; i < b1; i++) s += g_deg[i];
        sh[tid] = s;
        __syncthreads();
        #pragma unroll
        for (int off = 1; off < 256; off <<= 1) {
            int v = (tid >= off) ? sh[tid - off] : 0;
            __syncthreads();
            sh[tid] += v;
            __syncthreads();
        }
        int run = (tid > 0) ? sh[tid - 1] : 0;
        for (int i = b0; i < b1; i++) {
            g_ptr[i] = run; g_off[i] = run;
            run += g_deg[i];
        }
        if (tid == 0) g_ptr[NN] = NE;
        __syncthreads();
        __threadfence();
        if (tid == 0) atomicExch(&g_scan_done, 1);
    } else {
        // weight transpose + tf32 conversion over 2*NL*DD*DD = 131072 elems
        for (int i = (blockIdx.x - 1) * 256 + tid; i < 2 * NL * DD * DD;
             i += 147 * 256) {
            int which = i / (NL * DD * DD);
            int r = i % (NL * DD * DD);
            int l = r / (DD * DD);
            int e = r % (DD * DD);
            int k = e / DD, n = e % DD;
            const float* w = which ? W2 : W1;
            g_Wt[which][l][n * AST + k] = f2tf32(w[l * DD * DD + k * DD + n]);
        }
        if (tid == 0) {
            while (atomicAdd(&g_scan_done, 0) == 0) __nanosleep(200);
        }
        __syncthreads();
    }
    // all blocks: scatter (grid-stride over edges)
    for (int i = blockIdx.x * 256 + tid; i < NE; i += 148 * 256) {
        int d = g_dst[i];
        int pos = atomicAdd(&g_off[d], 1);
        g_csr_src[pos] = g_src[i];
    }
}

// ---------------- mma.sync tf32 GEMM (M tile = 64, 2 CTAs/SM) ----------------
// AGG=true:  A built in-kernel: (1+eps)*h + CSR neighbor sum; RELU output, no stats
// AGG=false: A loaded from Ain; no relu, BN stats accumulated
#define SMEM_GEMM ((MT * AST + DD * AST) * 4)

template<bool AGG>
__global__ __launch_bounds__(256, 2)
void gemm_mma_kernel(const uint32_t* __restrict__ Wt,
                     const float* __restrict__ bias,
                     const float* __restrict__ Ain,
                     float* __restrict__ Cout,
                     const float* __restrict__ eps,
                     int l) {
    extern __shared__ __align__(16) uint32_t smem[];
    uint32_t* As = smem;             // [64][AST]
    uint32_t* Bs = smem + MT * AST;  // [128][AST] n-major
    int tid = threadIdx.x;
    int row0 = blockIdx.x * MT;
    int wid = tid >> 5, lane = tid & 31;

    // B: straight padded copy (already tf32 bits)
    #pragma unroll 4
    for (int i = tid; i < DD * AST / 4; i += 256)
        ((uint4*)Bs)[i] = ((const uint4*)Wt)[i];

    if (AGG) {
        // warp w builds rows [w*8, w*8+8); lane owns 4 channels
        float e = 1.0f + __ldg(&eps[l]);
        const float4* hv = (const float4*)Ain;
        #pragma unroll
        for (int rr = 0; rr < 8; rr++) {
            int m = wid * 8 + rr;
            int gm = row0 + m;
            float4 acc = make_float4(0.f, 0.f, 0.f, 0.f);
            if (gm < NN) {
                float4 a = __ldg(&hv[(size_t)gm * 32 + lane]);
                acc = make_float4(a.x * e, a.y * e, a.z * e, a.w * e);
                int p = __ldg(&g_ptr[gm]);
                int p1 = __ldg(&g_ptr[gm + 1]);
                for (; p + 2 <= p1; p += 2) {
                    int s0 = __ldg(&g_csr_src[p]);
                    int s1 = __ldg(&g_csr_src[p + 1]);
                    float4 v0 = __ldg(&hv[(size_t)s0 * 32 + lane]);
                    float4 v1 = __ldg(&hv[(size_t)s1 * 32 + lane]);
                    acc.x += v0.x + v1.x; acc.y += v0.y + v1.y;
                    acc.z += v0.z + v1.z; acc.w += v0.w + v1.w;
                }
                if (p < p1) {
                    int s = __ldg(&g_csr_src[p]);
                    float4 v = __ldg(&hv[(size_t)s * 32 + lane]);
                    acc.x += v.x; acc.y += v.y; acc.z += v.z; acc.w += v.w;
                }
            }
            uint32_t* pA = &As[m * AST + lane * 4];
            pA[0] = f2tf32(acc.x); pA[1] = f2tf32(acc.y);
            pA[2] = f2tf32(acc.z); pA[3] = f2tf32(acc.w);
        }
    } else {
        #pragma unroll 2
        for (int i = tid; i < MT * 32; i += 256) {
            int m = i >> 5;
            int k4 = i & 31;
            int gm = row0 + m;
            float4 v = make_float4(0.f, 0.f, 0.f, 0.f);
            if (gm < NN) v = __ldg(&((const float4*)(Ain + (size_t)gm * DD))[k4]);
            uint32_t* p = &As[m * AST + k4 * 4];
            p[0] = f2tf32(v.x); p[1] = f2tf32(v.y);
            p[2] = f2tf32(v.z); p[3] = f2tf32(v.w);
        }
    }
    __syncthreads();

    int wm = (wid & 1) * 32;
    int wn = (wid >> 1) * 32;
    int grp = lane >> 2, qid = lane & 3;

    float acc[2][4][4];
    #pragma unroll
    for (int i = 0; i < 2; i++)
        #pragma unroll
        for (int j = 0; j < 4; j++)
            #pragma unroll
            for (int q = 0; q < 4; q++) acc[i][j][q] = 0.f;

    #pragma unroll
    for (int ks = 0; ks < 16; ks++) {
        int k0 = ks * 8;
        uint32_t a[2][4];
        #pragma unroll
        for (int mt = 0; mt < 2; mt++) {
            int r = wm + mt * 16;
            a[mt][0] = As[(r + grp) * AST + k0 + qid];
            a[mt][1] = As[(r + grp + 8) * AST + k0 + qid];
            a[mt][2] = As[(r + grp) * AST + k0 + qid + 4];
            a[mt][3] = As[(r + grp + 8) * AST + k0 + qid + 4];
        }
        #pragma unroll
        for (int nt = 0; nt < 4; nt++) {
            uint32_t b0 = Bs[(wn + nt * 8 + grp) * AST + k0 + qid];
            uint32_t b1 = Bs[(wn + nt * 8 + grp) * AST + k0 + qid + 4];
            #pragma unroll
            for (int mt = 0; mt < 2; mt++)
                mma_tf32(acc[mt][nt][0], acc[mt][nt][1], acc[mt][nt][2], acc[mt][nt][3],
                         a[mt][0], a[mt][1], a[mt][2], a[mt][3], b0, b1);
        }
    }

    #pragma unroll
    for (int nt = 0; nt < 4; nt++) {
        int col = wn + nt * 8 + 2 * qid;
        float bv0 = __ldg(&bias[col]);
        float bv1 = __ldg(&bias[col + 1]);
        float s0 = 0.f, s1 = 0.f, q0 = 0.f, q1 = 0.f;
        #pragma unroll
        for (int mt = 0; mt < 2; mt++) {
            int r = row0 + wm + mt * 16 + grp;
            float v0 = acc[mt][nt][0] + bv0;
            float v1 = acc[mt][nt][1] + bv1;
            float v2 = acc[mt][nt][2] + bv0;
            float v3 = acc[mt][nt][3] + bv1;
            if (AGG) {   // relu for MLP hidden
                v0 = fmaxf(v0, 0.f); v1 = fmaxf(v1, 0.f);
                v2 = fmaxf(v2, 0.f); v3 = fmaxf(v3, 0.f);
            }
            if (r < NN) {
                *(float2*)(Cout + (size_t)r * DD + col) = make_float2(v0, v1);
                if (!AGG) { s0 += v0; s1 += v1; q0 += v0 * v0; q1 += v1 * v1; }
            }
            if (r + 8 < NN) {
                *(float2*)(Cout + (size_t)(r + 8) * DD + col) = make_float2(v2, v3);
                if (!AGG) { s0 += v2; s1 += v3; q0 += v2 * v2; q1 += v3 * v3; }
            }
        }
        if (!AGG) {
            #pragma unroll
            for (int m = 4; m < 32; m <<= 1) {
                s0 += __shfl_xor_sync(0xFFFFFFFF, s0, m);
                s1 += __shfl_xor_sync(0xFFFFFFFF, s1, m);
                q0 += __shfl_xor_sync(0xFFFFFFFF, q0, m);
                q1 += __shfl_xor_sync(0xFFFFFFFF, q1, m);
            }
            if (grp == 0) {
                atomicAdd(&g_sum[l * DD + col], s0);
                atomicAdd(&g_sum[l * DD + col + 1], s1);
                atomicAdd(&g_sqs[l * DD + col], q0);
                atomicAdd(&g_sqs[l * DD + col + 1], q1);
            }
        }
    }
}

// ---------------- BN finalize + relu + pool (fused) ----------------
__global__ void bn_relu_pool_kernel(const float* __restrict__ gamma,
                                    const float* __restrict__ beta, int l) {
    __shared__ float s_sc[DD], s_sf[DD];
    int tid = threadIdx.x;
    if (tid < DD) {
        float mean = g_sum[l * DD + tid] * (1.0f / NN);
        float var = g_sqs[l * DD + tid] * (1.0f / NN) - mean * mean;
        float sc = __ldg(&gamma[l * DD + tid]) * rsqrtf(var + 1e-5f);
        s_sc[tid] = sc;
        s_sf[tid] = __ldg(&beta[l * DD + tid]) - mean * sc;
    }
    __syncthreads();
    int i = blockIdx.x * blockDim.x + tid;
    if (i >= NN * DD / 4) return;
    int r = i >> 5;
    int c4 = (i & 31) << 2;
    float4 z = ((const float4*)g_Z)[i];
    float4 hv;
    hv.x = fmaxf(z.x * s_sc[c4]     + s_sf[c4],     0.f);
    hv.y = fmaxf(z.y * s_sc[c4 + 1] + s_sf[c4 + 1], 0.f);
    hv.z = fmaxf(z.z * s_sc[c4 + 2] + s_sf[c4 + 2], 0.f);
    hv.w = fmaxf(z.w * s_sc[c4 + 3] + s_sf[c4 + 3], 0.f);
    ((float4*)g_H)[i] = hv;
    int b = __ldg(&g_batch[r]);
    red_add_v4(&g_pool[(size_t)b * (NL * DD) + l * DD + c4], hv);
}

// ---------------- final linear ----------------
__global__ void final_kernel(const float* __restrict__ Wlin,
                             const float* __restrict__ blin,
                             float* __restrict__ out) {
    int t = blockIdx.x * blockDim.x + threadIdx.x;
    if (t >= NG * NC) return;
    int gph = t / NC, c = t % NC;
    float acc = __ldg(&blin[c]);
    const float* prow = &g_pool[(size_t)gph * (NL * DD)];
    #pragma unroll 8
    for (int k = 0; k < NL * DD; k++)
        acc += __ldg(&prow[k]) * __ldg(&Wlin[k * NC + c]);
    out[gph * NC + c] = acc;
}

extern "C" void kernel_launch(void* const* d_in, const int* in_sizes, int n_in,
                              void* d_out, int out_size) {
    const float* x     = (const float*)d_in[0];
    const int*   ei32  = (const int*)d_in[1];
    const int*   b32   = (const int*)d_in[2];
    const float* W1    = (const float*)d_in[3];
    const float* b1    = (const float*)d_in[4];
    const float* W2    = (const float*)d_in[5];
    const float* b2    = (const float*)d_in[6];
    const float* eps   = (const float*)d_in[7];
    const float* gamma = (const float*)d_in[8];
    const float* beta  = (const float*)d_in[9];
    const float* Wlin  = (const float*)d_in[10];
    const float* blin  = (const float*)d_in[11];
    float* out = (float*)d_out;

    cudaFuncSetAttribute(gemm_mma_kernel<true>,
                         cudaFuncAttributeMaxDynamicSharedMemorySize, SMEM_GEMM);
    cudaFuncSetAttribute(gemm_mma_kernel<false>,
                         cudaFuncAttributeMaxDynamicSharedMemorySize, SMEM_GEMM);

    // init via memset nodes (not kernel launches)
    void *p_mode_ei, *p_mode_b, *p_deg, *p_pool, *p_sum, *p_sqs, *p_done;
    cudaGetSymbolAddress(&p_mode_ei, g_mode_ei);
    cudaGetSymbolAddress(&p_mode_b,  g_mode_b);
    cudaGetSymbolAddress(&p_deg,     g_deg);
    cudaGetSymbolAddress(&p_pool,    g_pool);
    cudaGetSymbolAddress(&p_sum,     g_sum);
    cudaGetSymbolAddress(&p_sqs,     g_sqs);
    cudaGetSymbolAddress(&p_done,    g_scan_done);
    cudaMemsetAsync(p_mode_ei, 1, 4);
    cudaMemsetAsync(p_mode_b,  1, 4);
    cudaMemsetAsync(p_done,    0, 4);
    cudaMemsetAsync(p_deg,  0, NN * sizeof(int));
    cudaMemsetAsync(p_pool, 0, NG * NL * DD * sizeof(float));
    cudaMemsetAsync(p_sum,  0, NL * DD * sizeof(float));
    cudaMemsetAsync(p_sqs,  0, NL * DD * sizeof(float));

    detect_kernel<<<(NE + 255) / 256, 256>>>(ei32, b32);            // launch 0
    convert_hist_kernel<<<(NE + 255) / 256, 256>>>(ei32, b32);      // launch 1
    scan_wprep_scatter_kernel<<<148, 256>>>(W1, W2);                // launch 2

    int zgrid = (NN * DD / 4 + 255) / 256;

    uint32_t* wt_base;
    cudaGetSymbolAddress((void**)&wt_base, g_Wt);
    float *zb, *tb, *hb;
    cudaGetSymbolAddress((void**)&zb, g_Z);
    cudaGetSymbolAddress((void**)&tb, g_T);
    cudaGetSymbolAddress((void**)&hb, g_H);

    for (int l = 0; l < NL; l++) {
        const float* hsrc = l ? hb : x;
        // launch 3 (l=0) -> profiled: fused agg + T = relu(Z@W1+b1)
        gemm_mma_kernel<true><<<NTILES, 256, SMEM_GEMM>>>(
            wt_base + (size_t)l * DD * AST, b1 + l * DD, hsrc, tb, eps, l);
        // Z = T@W2+b2 (+BN stats)
        gemm_mma_kernel<false><<<NTILES, 256, SMEM_GEMM>>>(
            wt_base + (size_t)(NL + l) * DD * AST, b2 + l * DD, tb, zb, eps, l);
        bn_relu_pool_kernel<<<zgrid, 256>>>(gamma, beta, l);
    }
    final_kernel<<<(NG * NC + 255) / 256, 256>>>(Wlin, blin, out);
}

// round 12
// speedup vs baseline: 1.0236x; 1.0236x over previous
#include <cuda_runtime.h>
#include <cstdint>

#define NN 50000
#define NE 600000
#define DD 128
#define NL 4
#define NG 512
#define NC 10
#define AST 136        // padded smem stride (floats); 136 mod 32 = 8 -> LDS.64 conflict-free
#define MT 64          // GEMM M tile
#define NTILES ((NN + MT - 1) / MT)   // 782

// ---- scratch (device globals: allocation-free) ----
__device__ float g_H[NN * DD];
__device__ float g_Z[NN * DD];
__device__ float g_T[NN * DD];
__device__ float g_sum[NL * DD];
__device__ float g_sqs[NL * DD];
__device__ float g_pool[NG * NL * DD];
__device__ uint32_t g_Wt[2][NL][DD * AST];   // transposed, pair-permuted, tf32

__device__ int g_src[NE];
__device__ int g_dst[NE];
__device__ int g_batch[NN];
__device__ int g_deg[NN];
__device__ int g_ptr[NN + 1];
__device__ int g_off[NN];
__device__ int g_csr_src[NE];
__device__ int g_mode_ei;
__device__ int g_mode_b;
__device__ int g_scan_done;
__device__ int g_arrive;

__device__ __forceinline__ void red_add_v4(float* p, float4 v) {
    asm volatile("red.global.add.v4.f32 [%0], {%1, %2, %3, %4};"
                 :: "l"(p), "f"(v.x), "f"(v.y), "f"(v.z), "f"(v.w)
                 : "memory");
}
__device__ __forceinline__ uint32_t f2tf32(float f) {
    uint32_t u;
    asm("cvt.rna.tf32.f32 %0, %1;" : "=r"(u) : "f"(f));
    return u;
}
__device__ __forceinline__ void mma_tf32(float& c0, float& c1, float& c2, float& c3,
                                         uint32_t a0, uint32_t a1, uint32_t a2, uint32_t a3,
                                         uint32_t b0, uint32_t b1) {
    asm volatile(
        "mma.sync.aligned.m16n8k8.row.col.f32.tf32.tf32.f32 "
        "{%0,%1,%2,%3}, {%4,%5,%6,%7}, {%8,%9}, {%0,%1,%2,%3};"
        : "+f"(c0), "+f"(c1), "+f"(c2), "+f"(c3)
        : "r"(a0), "r"(a1), "r"(a2), "r"(a3), "r"(b0), "r"(b1));
}
// pair-permuted slot of k within a row: (k,k+4) become adjacent 64-bit pairs
__device__ __forceinline__ int kperm(int k) {
    return (k & ~7) + ((k & 3) << 1) + ((k >> 2) & 1);
}

// ---------------- preamble ----------------
// persistent (148 CTAs): phase 1 detect dtype, global sync, phase 2 convert + hist
__global__ __launch_bounds__(256)
void detect_convert_kernel(const int* __restrict__ ei32,
                           const int* __restrict__ b32) {
    int tid = threadIdx.x;
    const int STRIDE = 148 * 256;
    for (int i = blockIdx.x * 256 + tid; i < NE; i += STRIDE) {
        int idx = 2 * i + 1;
        if (idx < 2 * NE && ei32[idx] != 0) atomicExch(&g_mode_ei, 0);
        if (idx < NN && b32[idx] != 0)      atomicExch(&g_mode_b, 0);
    }
    __syncthreads();
    __threadfence();
    if (tid == 0) {
        atomicAdd(&g_arrive, 1);
        while (atomicAdd(&g_arrive, 0) < 148) __nanosleep(100);
    }
    __syncthreads();
    int m_ei = atomicAdd(&g_mode_ei, 0);
    int m_b  = atomicAdd(&g_mode_b, 0);
    for (int i = blockIdx.x * 256 + tid; i < NE; i += STRIDE) {
        int s = m_ei ? ei32[2 * i]        : ei32[i];
        int d = m_ei ? ei32[2 * (NE + i)] : ei32[NE + i];
        g_src[i] = s;
        g_dst[i] = d;
        atomicAdd(&g_deg[d], 1);
        if (i < NN) g_batch[i] = m_b ? b32[2 * i] : b32[i];
    }
}

// persistent: block 0 scans degrees; others do weight prep; flag-sync; all scatter
__global__ __launch_bounds__(256)
void scan_wprep_scatter_kernel(const float* __restrict__ W1,
                               const float* __restrict__ W2) {
    int tid = threadIdx.x;
    if (blockIdx.x == 0) {
        __shared__ int sh[256];
        const int CH = (NN + 255) / 256;
        int b0 = tid * CH, b1 = min(b0 + CH, NN);
        int s = 0;
        for (int i = b0; i < b1; i++) s += g_deg[i];
        sh[tid] = s;
        __syncthreads();
        #pragma unroll
        for (int off = 1; off < 256; off <<= 1) {
            int v = (tid >= off) ? sh[tid - off] : 0;
            __syncthreads();
            sh[tid] += v;
            __syncthreads();
        }
        int run = (tid > 0) ? sh[tid - 1] : 0;
        for (int i = b0; i < b1; i++) {
            g_ptr[i] = run; g_off[i] = run;
            run += g_deg[i];
        }
        if (tid == 0) g_ptr[NN] = NE;
        __syncthreads();
        __threadfence();
        if (tid == 0) atomicExch(&g_scan_done, 1);
    } else {
        for (int i = (blockIdx.x - 1) * 256 + tid; i < 2 * NL * DD * DD;
             i += 147 * 256) {
            int which = i / (NL * DD * DD);
            int r = i % (NL * DD * DD);
            int l = r / (DD * DD);
            int e = r % (DD * DD);
            int k = e / DD, n = e % DD;
            const float* w = which ? W2 : W1;
            g_Wt[which][l][n * AST + kperm(k)] = f2tf32(w[l * DD * DD + k * DD + n]);
        }
        if (tid == 0) {
            while (atomicAdd(&g_scan_done, 0) == 0) __nanosleep(200);
        }
        __syncthreads();
    }
    for (int i = blockIdx.x * 256 + tid; i < NE; i += 148 * 256) {
        int d = g_dst[i];
        int pos = atomicAdd(&g_off[d], 1);
        g_csr_src[pos] = g_src[i];
    }
}

// ---------------- fused (1+eps)*h + CSR neighbor-sum (high occupancy) ----------------
__global__ void agg_kernel(const float* __restrict__ x,
                           const float* __restrict__ eps, int l) {
    int warp = (blockIdx.x * blockDim.x + threadIdx.x) >> 5;
    if (warp >= NN) return;
    int lane = threadIdx.x & 31;
    const float* h = l ? g_H : x;
    const float4* hv = (const float4*)h;
    float e = 1.0f + __ldg(&eps[l]);
    float4 a = hv[warp * 32 + lane];
    float4 acc = make_float4(a.x * e, a.y * e, a.z * e, a.w * e);
    int p = __ldg(&g_ptr[warp]);
    int p1 = __ldg(&g_ptr[warp + 1]);
    for (; p + 4 <= p1; p += 4) {
        int s0 = __ldg(&g_csr_src[p]);
        int s1 = __ldg(&g_csr_src[p + 1]);
        int s2 = __ldg(&g_csr_src[p + 2]);
        int s3 = __ldg(&g_csr_src[p + 3]);
        float4 v0 = __ldg(&hv[s0 * 32 + lane]);
        float4 v1 = __ldg(&hv[s1 * 32 + lane]);
        float4 v2 = __ldg(&hv[s2 * 32 + lane]);
        float4 v3 = __ldg(&hv[s3 * 32 + lane]);
        acc.x += v0.x + v1.x + v2.x + v3.x;
        acc.y += v0.y + v1.y + v2.y + v3.y;
        acc.z += v0.z + v1.z + v2.z + v3.z;
        acc.w += v0.w + v1.w + v2.w + v3.w;
    }
    for (; p < p1; p++) {
        int s = __ldg(&g_csr_src[p]);
        float4 v = __ldg(&hv[s * 32 + lane]);
        acc.x += v.x; acc.y += v.y; acc.z += v.z; acc.w += v.w;
    }
    ((float4*)g_Z)[warp * 32 + lane] = acc;
}

// ---------------- mma.sync tf32 GEMM: pair-permuted layout, LDS.64 frags,
// explicit 2-stage register pipeline. M tile 64, 2 CTAs/SM. ----------------
#define SMEM_GEMM ((MT + DD) * AST * 4)

template<bool RELU, bool STATS>
__global__ __launch_bounds__(256, 2)
void gemm_mma_kernel(const uint32_t* __restrict__ Wt,
                     const float* __restrict__ bias,
                     const float* __restrict__ Ain,
                     float* __restrict__ Cout,
                     int l) {
    extern __shared__ __align__(16) uint32_t smem[];
    uint32_t* As = smem;             // [64][AST], pair-permuted k
    uint32_t* Bs = smem + MT * AST;  // [128][AST], n-major, pair-permuted k
    int tid = threadIdx.x;
    int row0 = blockIdx.x * MT;

    // B: straight copy (already permuted tf32 bits)
    #pragma unroll 4
    for (int i = tid; i < DD * AST / 4; i += 256)
        ((uint4*)Bs)[i] = ((const uint4*)Wt)[i];
    // A: row-major load, tf32 convert, pair-permute store
    #pragma unroll 2
    for (int i = tid; i < MT * 32; i += 256) {
        int m = i >> 5;
        int k4 = i & 31;
        int gm = row0 + m;
        float4 v = make_float4(0.f, 0.f, 0.f, 0.f);
        if (gm < NN) v = __ldg(&((const float4*)(Ain + (size_t)gm * DD))[k4]);
        uint32_t* p = &As[m * AST + (k4 >> 1) * 8 + (k4 & 1)];
        p[0] = f2tf32(v.x); p[2] = f2tf32(v.y);
        p[4] = f2tf32(v.z); p[6] = f2tf32(v.w);
    }
    __syncthreads();

    int wid = tid >> 5, lane = tid & 31;
    int wm = (wid & 1) * 32;
    int wn = (wid >> 1) * 32;
    int grp = lane >> 2, qid = lane & 3;

    const uint32_t* Arow0 = &As[(wm + grp) * AST + qid * 2];
    const uint32_t* Arow1 = Arow0 + 8 * AST;
    const uint32_t* Arow2 = Arow0 + 16 * AST;
    const uint32_t* Arow3 = Arow0 + 24 * AST;
    const uint32_t* Brow0 = &Bs[(wn + grp) * AST + qid * 2];

    float acc[2][4][4];
    #pragma unroll
    for (int i = 0; i < 2; i++)
        #pragma unroll
        for (int j = 0; j < 4; j++)
            #pragma unroll
            for (int q = 0; q < 4; q++) acc[i][j][q] = 0.f;

    uint2 a_cur[4], b_cur[4], a_nxt[4], b_nxt[4];
    a_cur[0] = *(const uint2*)(Arow0);
    a_cur[1] = *(const uint2*)(Arow1);
    a_cur[2] = *(const uint2*)(Arow2);
    a_cur[3] = *(const uint2*)(Arow3);
    #pragma unroll
    for (int nt = 0; nt < 4; nt++)
        b_cur[nt] = *(const uint2*)(Brow0 + nt * 8 * AST);

    #pragma unroll
    for (int ks = 0; ks < 16; ks++) {
        if (ks < 15) {
            int off = (ks + 1) * 8;
            a_nxt[0] = *(const uint2*)(Arow0 + off);
            a_nxt[1] = *(const uint2*)(Arow1 + off);
            a_nxt[2] = *(const uint2*)(Arow2 + off);
            a_nxt[3] = *(const uint2*)(Arow3 + off);
            #pragma unroll
            for (int nt = 0; nt < 4; nt++)
                b_nxt[nt] = *(const uint2*)(Brow0 + nt * 8 * AST + off);
        }
        #pragma unroll
        for (int nt = 0; nt < 4; nt++) {
            mma_tf32(acc[0][nt][0], acc[0][nt][1], acc[0][nt][2], acc[0][nt][3],
                     a_cur[0].x, a_cur[1].x, a_cur[0].y, a_cur[1].y,
                     b_cur[nt].x, b_cur[nt].y);
            mma_tf32(acc[1][nt][0], acc[1][nt][1], acc[1][nt][2], acc[1][nt][3],
                     a_cur[2].x, a_cur[3].x, a_cur[2].y, a_cur[3].y,
                     b_cur[nt].x, b_cur[nt].y);
        }
        #pragma unroll
        for (int j = 0; j < 4; j++) { a_cur[j] = a_nxt[j]; b_cur[j] = b_nxt[j]; }
    }

    #pragma unroll
    for (int nt = 0; nt < 4; nt++) {
        int col = wn + nt * 8 + 2 * qid;
        float bv0 = __ldg(&bias[col]);
        float bv1 = __ldg(&bias[col + 1]);
        float s0 = 0.f, s1 = 0.f, q0 = 0.f, q1 = 0.f;
        #pragma unroll
        for (int mt = 0; mt < 2; mt++) {
            int r = row0 + wm + mt * 16 + grp;
            float v0 = acc[mt][nt][0] + bv0;
            float v1 = acc[mt][nt][1] + bv1;
            float v2 = acc[mt][nt][2] + bv0;
            float v3 = acc[mt][nt][3] + bv1;
            if (RELU) {
                v0 = fmaxf(v0, 0.f); v1 = fmaxf(v1, 0.f);
                v2 = fmaxf(v2, 0.f); v3 = fmaxf(v3, 0.f);
            }
            if (r < NN) {
                *(float2*)(Cout + (size_t)r * DD + col) = make_float2(v0, v1);
                if (STATS) { s0 += v0; s1 += v1; q0 += v0 * v0; q1 += v1 * v1; }
            }
            if (r + 8 < NN) {
                *(float2*)(Cout + (size_t)(r + 8) * DD + col) = make_float2(v2, v3);
                if (STATS) { s0 += v2; s1 += v3; q0 += v2 * v2; q1 += v3 * v3; }
            }
        }
        if (STATS) {
            #pragma unroll
            for (int m = 4; m < 32; m <<= 1) {
                s0 += __shfl_xor_sync(0xFFFFFFFF, s0, m);
                s1 += __shfl_xor_sync(0xFFFFFFFF, s1, m);
                q0 += __shfl_xor_sync(0xFFFFFFFF, q0, m);
                q1 += __shfl_xor_sync(0xFFFFFFFF, q1, m);
            }
            if (grp == 0) {
                atomicAdd(&g_sum[l * DD + col], s0);
                atomicAdd(&g_sum[l * DD + col + 1], s1);
                atomicAdd(&g_sqs[l * DD + col], q0);
                atomicAdd(&g_sqs[l * DD + col + 1], q1);
            }
        }
    }
}

// ---------------- BN finalize + relu + pool (block-local pooling) ----------------
// NN % 8 == 0, so every 256-thread block covers exactly 8 full rows.
__global__ void bn_relu_pool_kernel(const float* __restrict__ gamma,
                                    const float* __restrict__ beta, int l) {
    __shared__ float s_sc[DD], s_sf[DD];
    __shared__ float4 buf[256];
    int tid = threadIdx.x;
    if (tid < DD) {
        float mean = g_sum[l * DD + tid] * (1.0f / NN);
        float var = g_sqs[l * DD + tid] * (1.0f / NN) - mean * mean;
        float sc = __ldg(&gamma[l * DD + tid]) * rsqrtf(var + 1e-5f);
        s_sc[tid] = sc;
        s_sf[tid] = __ldg(&beta[l * DD + tid]) - mean * sc;
    }
    __syncthreads();
    int i = blockIdx.x * 256 + tid;
    int r = i >> 5;
    int c4 = (i & 31) << 2;
    float4 z = ((const float4*)g_Z)[i];
    float4 hv;
    hv.x = fmaxf(z.x * s_sc[c4]     + s_sf[c4],     0.f);
    hv.y = fmaxf(z.y * s_sc[c4 + 1] + s_sf[c4 + 1], 0.f);
    hv.z = fmaxf(z.z * s_sc[c4 + 2] + s_sf[c4 + 2], 0.f);
    hv.w = fmaxf(z.w * s_sc[c4 + 3] + s_sf[c4 + 3], 0.f);
    ((float4*)g_H)[i] = hv;

    int r0 = (blockIdx.x * 256) >> 5;
    int bfirst = __ldg(&g_batch[r0]);
    int blast  = __ldg(&g_batch[r0 + 7]);
    if (bfirst == blast) {
        // whole block same graph: reduce 8 rows -> 1 atomic per channel group
        buf[tid] = hv;
        __syncthreads();
        if (tid < 128) {
            buf[tid].x += buf[tid + 128].x; buf[tid].y += buf[tid + 128].y;
            buf[tid].z += buf[tid + 128].z; buf[tid].w += buf[tid + 128].w;
        }
        __syncthreads();
        if (tid < 64) {
            buf[tid].x += buf[tid + 64].x; buf[tid].y += buf[tid + 64].y;
            buf[tid].z += buf[tid + 64].z; buf[tid].w += buf[tid + 64].w;
        }
        __syncthreads();
        if (tid < 32) {
            float4 v = buf[tid];
            float4 w = buf[tid + 32];
            v.x += w.x; v.y += w.y; v.z += w.z; v.w += w.w;
            red_add_v4(&g_pool[(size_t)bfirst * (NL * DD) + l * DD + (tid << 2)], v);
        }
    } else {
        int b = __ldg(&g_batch[r]);
        red_add_v4(&g_pool[(size_t)b * (NL * DD) + l * DD + c4], hv);
    }
}

// ---------------- final linear ----------------
__global__ void final_kernel(const float* __restrict__ Wlin,
                             const float* __restrict__ blin,
                             float* __restrict__ out) {
    int t = blockIdx.x * blockDim.x + threadIdx.x;
    if (t >= NG * NC) return;
    int gph = t / NC, c = t % NC;
    float acc = __ldg(&blin[c]);
    const float* prow = &g_pool[(size_t)gph * (NL * DD)];
    #pragma unroll 8
    for (int k = 0; k < NL * DD; k++)
        acc += __ldg(&prow[k]) * __ldg(&Wlin[k * NC + c]);
    out[gph * NC + c] = acc;
}

extern "C" void kernel_launch(void* const* d_in, const int* in_sizes, int n_in,
                              void* d_out, int out_size) {
    const float* x     = (const float*)d_in[0];
    const int*   ei32  = (const int*)d_in[1];
    const int*   b32   = (const int*)d_in[2];
    const float* W1    = (const float*)d_in[3];
    const float* b1    = (const float*)d_in[4];
    const float* W2    = (const float*)d_in[5];
    const float* b2    = (const float*)d_in[6];
    const float* eps   = (const float*)d_in[7];
    const float* gamma = (const float*)d_in[8];
    const float* beta  = (const float*)d_in[9];
    const float* Wlin  = (const float*)d_in[10];
    const float* blin  = (const float*)d_in[11];
    float* out = (float*)d_out;

    cudaFuncSetAttribute(gemm_mma_kernel<true, false>,
                         cudaFuncAttributeMaxDynamicSharedMemorySize, SMEM_GEMM);
    cudaFuncSetAttribute(gemm_mma_kernel<false, true>,
                         cudaFuncAttributeMaxDynamicSharedMemorySize, SMEM_GEMM);

    // init via memset nodes (not kernel launches)
    void *p_mode_ei, *p_mode_b, *p_deg, *p_pool, *p_sum, *p_sqs, *p_done, *p_arr;
    cudaGetSymbolAddress(&p_mode_ei, g_mode_ei);
    cudaGetSymbolAddress(&p_mode_b,  g_mode_b);
    cudaGetSymbolAddress(&p_deg,     g_deg);
    cudaGetSymbolAddress(&p_pool,    g_pool);
    cudaGetSymbolAddress(&p_sum,     g_sum);
    cudaGetSymbolAddress(&p_sqs,     g_sqs);
    cudaGetSymbolAddress(&p_done,    g_scan_done);
    cudaGetSymbolAddress(&p_arr,     g_arrive);
    cudaMemsetAsync(p_mode_ei, 1, 4);
    cudaMemsetAsync(p_mode_b,  1, 4);
    cudaMemsetAsync(p_done,    0, 4);
    cudaMemsetAsync(p_arr,     0, 4);
    cudaMemsetAsync(p_deg,  0, NN * sizeof(int));
    cudaMemsetAsync(p_pool, 0, NG * NL * DD * sizeof(float));
    cudaMemsetAsync(p_sum,  0, NL * DD * sizeof(float));
    cudaMemsetAsync(p_sqs,  0, NL * DD * sizeof(float));

    detect_convert_kernel<<<148, 256>>>(ei32, b32);                 // launch 0
    scan_wprep_scatter_kernel<<<148, 256>>>(W1, W2);                // launch 1

    int zgrid = NN * DD / 4 / 256;         // 6250 (exact)
    int agrid = (NN * 32 + 255) / 256;

    uint32_t* wt_base;
    cudaGetSymbolAddress((void**)&wt_base, g_Wt);
    float *zb, *tb;
    cudaGetSymbolAddress((void**)&zb, g_Z);
    cudaGetSymbolAddress((void**)&tb, g_T);

    for (int l = 0; l < NL; l++) {
        agg_kernel<<<agrid, 256>>>(x, eps, l);                      // launch 2 (l=0)
        gemm_mma_kernel<true, false><<<NTILES, 256, SMEM_GEMM>>>(
            wt_base + (size_t)l * DD * AST, b1 + l * DD, zb, tb, l);      // launch 3 -> ncu
        gemm_mma_kernel<false, true><<<NTILES, 256, SMEM_GEMM>>>(
            wt_base + (size_t)(NL + l) * DD * AST, b2 + l * DD, tb, zb, l);
        bn_relu_pool_kernel<<<zgrid, 256>>>(gamma, beta, l);
    }
    final_kernel<<<(NG * NC + 255) / 256, 256>>>(Wlin, blin, out);
}

// round 13
// speedup vs baseline: 1.7406x; 1.7004x over previous
#include <cuda_runtime.h>
#include <cstdint>

#define NN 50000
#define NE 600000
#define DD 128
#define NL 4
#define NG 512
#define NC 10
#define AST 136        // padded smem stride (floats); 136 mod 32 = 8 -> LDS.64 conflict-free
#define MT 64          // GEMM M tile
#define NTILES ((NN + MT - 1) / MT)   // 782

// ---- scratch (device globals: allocation-free) ----
__device__ float g_H[NN * DD];
__device__ float g_Z[NN * DD];
__device__ float g_T[NN * DD];
__device__ float g_sum[NL * DD];
__device__ float g_sqs[NL * DD];
__device__ float g_pool[NG * NL * DD];
__device__ uint32_t g_Wt[2][NL][DD * AST];   // transposed, pair-permuted, tf32

__device__ int g_src[NE];
__device__ int g_dst[NE];
__device__ int g_batch[NN];
__device__ int g_deg[NN];
__device__ int g_ptr[NN + 1];
__device__ int g_off[NN];
__device__ int g_csr_src[NE];
__device__ int g_mode_ei;
__device__ int g_mode_b;
__device__ int g_bar[3];

__device__ __forceinline__ void red_add_v4(float* p, float4 v) {
    asm volatile("red.global.add.v4.f32 [%0], {%1, %2, %3, %4};"
                 :: "l"(p), "f"(v.x), "f"(v.y), "f"(v.z), "f"(v.w)
                 : "memory");
}
__device__ __forceinline__ uint32_t f2tf32(float f) {
    uint32_t u;
    asm("cvt.rna.tf32.f32 %0, %1;" : "=r"(u) : "f"(f));
    return u;
}
__device__ __forceinline__ void mma_tf32(float& c0, float& c1, float& c2, float& c3,
                                         uint32_t a0, uint32_t a1, uint32_t a2, uint32_t a3,
                                         uint32_t b0, uint32_t b1) {
    asm volatile(
        "mma.sync.aligned.m16n8k8.row.col.f32.tf32.tf32.f32 "
        "{%0,%1,%2,%3}, {%4,%5,%6,%7}, {%8,%9}, {%0,%1,%2,%3};"
        : "+f"(c0), "+f"(c1), "+f"(c2), "+f"(c3)
        : "r"(a0), "r"(a1), "r"(a2), "r"(a3), "r"(b0), "r"(b1));
}
// pair-permuted slot of k within a row: (k,k+4) become adjacent 64-bit pairs
__device__ __forceinline__ int kperm(int k) {
    return (k & ~7) + ((k & 3) << 1) + ((k >> 2) & 1);
}

// ---------------- single persistent preamble kernel (148 CTAs) ----------------
__device__ __forceinline__ void gbarrier(int idx) {
    __syncthreads();
    __threadfence();
    if (threadIdx.x == 0) {
        atomicAdd(&g_bar[idx], 1);
        while (atomicAdd(&g_bar[idx], 0) < 148) __nanosleep(64);
    }
    __syncthreads();
}

__global__ __launch_bounds__(256)
void preamble_kernel(const int* __restrict__ ei32,
                     const int* __restrict__ b32,
                     const float* __restrict__ W1,
                     const float* __restrict__ W2) {
    int tid = threadIdx.x;
    const int STRIDE = 148 * 256;

    // phase 1: dtype detection (block-reduced, 1 atomic per block)
    int nz_ei = 0, nz_b = 0;
    for (int i = blockIdx.x * 256 + tid; i < NE; i += STRIDE) {
        if (ei32[2 * i + 1] != 0) nz_ei = 1;
        if (2 * i + 1 < NN && b32[2 * i + 1] != 0) nz_b = 1;
    }
    int any_ei = __syncthreads_or(nz_ei);
    int any_b  = __syncthreads_or(nz_b);
    if (tid == 0) {
        if (any_ei) atomicExch(&g_mode_ei, 0);
        if (any_b)  atomicExch(&g_mode_b, 0);
    }
    gbarrier(0);

    // phase 2: convert + degree histogram
    int m_ei = atomicAdd(&g_mode_ei, 0);
    int m_b  = atomicAdd(&g_mode_b, 0);
    for (int i = blockIdx.x * 256 + tid; i < NE; i += STRIDE) {
        int s = m_ei ? ei32[2 * i]        : ei32[i];
        int d = m_ei ? ei32[2 * (NE + i)] : ei32[NE + i];
        g_src[i] = s;
        g_dst[i] = d;
        atomicAdd(&g_deg[d], 1);
        if (i < NN) g_batch[i] = m_b ? b32[2 * i] : b32[i];
    }
    gbarrier(1);

    // phase 3: block 0 scans degrees; others transpose/tf32-prep weights
    if (blockIdx.x == 0) {
        __shared__ int sh[256];
        const int CH = (NN + 255) / 256;
        int b0 = tid * CH, b1 = min(b0 + CH, NN);
        int s = 0;
        for (int i = b0; i < b1; i++) s += g_deg[i];
        sh[tid] = s;
        __syncthreads();
        #pragma unroll
        for (int off = 1; off < 256; off <<= 1) {
            int v = (tid >= off) ? sh[tid - off] : 0;
            __syncthreads();
            sh[tid] += v;
            __syncthreads();
        }
        int run = (tid > 0) ? sh[tid - 1] : 0;
        for (int i = b0; i < b1; i++) {
            g_ptr[i] = run; g_off[i] = run;
            run += g_deg[i];
        }
        if (tid == 0) g_ptr[NN] = NE;
    } else {
        for (int i = (blockIdx.x - 1) * 256 + tid; i < 2 * NL * DD * DD;
             i += 147 * 256) {
            int which = i / (NL * DD * DD);
            int r = i % (NL * DD * DD);
            int l = r / (DD * DD);
            int e = r % (DD * DD);
            int k = e / DD, n = e % DD;
            const float* w = which ? W2 : W1;
            g_Wt[which][l][n * AST + kperm(k)] = f2tf32(w[l * DD * DD + k * DD + n]);
        }
    }
    gbarrier(2);

    // phase 4: scatter edges into CSR
    for (int i = blockIdx.x * 256 + tid; i < NE; i += STRIDE) {
        int d = g_dst[i];
        int pos = atomicAdd(&g_off[d], 1);
        g_csr_src[pos] = g_src[i];
    }
}

// ---------------- fused (1+eps)*h + CSR neighbor-sum (high occupancy) ----------------
__global__ void agg_kernel(const float* __restrict__ x,
                           const float* __restrict__ eps, int l) {
    int warp = (blockIdx.x * blockDim.x + threadIdx.x) >> 5;
    if (warp >= NN) return;
    int lane = threadIdx.x & 31;
    const float* h = l ? g_H : x;
    const float4* hv = (const float4*)h;
    float e = 1.0f + __ldg(&eps[l]);
    float4 a = hv[warp * 32 + lane];
    float4 acc = make_float4(a.x * e, a.y * e, a.z * e, a.w * e);
    int p = __ldg(&g_ptr[warp]);
    int p1 = __ldg(&g_ptr[warp + 1]);
    for (; p + 4 <= p1; p += 4) {
        int s0 = __ldg(&g_csr_src[p]);
        int s1 = __ldg(&g_csr_src[p + 1]);
        int s2 = __ldg(&g_csr_src[p + 2]);
        int s3 = __ldg(&g_csr_src[p + 3]);
        float4 v0 = __ldg(&hv[s0 * 32 + lane]);
        float4 v1 = __ldg(&hv[s1 * 32 + lane]);
        float4 v2 = __ldg(&hv[s2 * 32 + lane]);
        float4 v3 = __ldg(&hv[s3 * 32 + lane]);
        acc.x += v0.x + v1.x + v2.x + v3.x;
        acc.y += v0.y + v1.y + v2.y + v3.y;
        acc.z += v0.z + v1.z + v2.z + v3.z;
        acc.w += v0.w + v1.w + v2.w + v3.w;
    }
    for (; p < p1; p++) {
        int s = __ldg(&g_csr_src[p]);
        float4 v = __ldg(&hv[s * 32 + lane]);
        acc.x += v.x; acc.y += v.y; acc.z += v.z; acc.w += v.w;
    }
    ((float4*)g_Z)[warp * 32 + lane] = acc;
}

// ---------------- mma.sync tf32 GEMM: pair-permuted layout, LDS.64 frags,
// explicit 2-stage register pipeline. M tile 64, 2 CTAs/SM. ----------------
#define SMEM_GEMM ((MT + DD) * AST * 4)

template<bool RELU, bool STATS>
__global__ __launch_bounds__(256, 2)
void gemm_mma_kernel(const uint32_t* __restrict__ Wt,
                     const float* __restrict__ bias,
                     const float* __restrict__ Ain,
                     float* __restrict__ Cout,
                     int l) {
    extern __shared__ __align__(16) uint32_t smem[];
    uint32_t* As = smem;             // [64][AST], pair-permuted k
    uint32_t* Bs = smem + MT * AST;  // [128][AST], n-major, pair-permuted k
    int tid = threadIdx.x;
    int row0 = blockIdx.x * MT;

    #pragma unroll 4
    for (int i = tid; i < DD * AST / 4; i += 256)
        ((uint4*)Bs)[i] = ((const uint4*)Wt)[i];
    #pragma unroll 2
    for (int i = tid; i < MT * 32; i += 256) {
        int m = i >> 5;
        int k4 = i & 31;
        int gm = row0 + m;
        float4 v = make_float4(0.f, 0.f, 0.f, 0.f);
        if (gm < NN) v = __ldg(&((const float4*)(Ain + (size_t)gm * DD))[k4]);
        uint32_t* p = &As[m * AST + (k4 >> 1) * 8 + (k4 & 1)];
        p[0] = f2tf32(v.x); p[2] = f2tf32(v.y);
        p[4] = f2tf32(v.z); p[6] = f2tf32(v.w);
    }
    __syncthreads();

    int wid = tid >> 5, lane = tid & 31;
    int wm = (wid & 1) * 32;
    int wn = (wid >> 1) * 32;
    int grp = lane >> 2, qid = lane & 3;

    const uint32_t* Arow0 = &As[(wm + grp) * AST + qid * 2];
    const uint32_t* Arow1 = Arow0 + 8 * AST;
    const uint32_t* Arow2 = Arow0 + 16 * AST;
    const uint32_t* Arow3 = Arow0 + 24 * AST;
    const uint32_t* Brow0 = &Bs[(wn + grp) * AST + qid * 2];

    float acc[2][4][4];
    #pragma unroll
    for (int i = 0; i < 2; i++)
        #pragma unroll
        for (int j = 0; j < 4; j++)
            #pragma unroll
            for (int q = 0; q < 4; q++) acc[i][j][q] = 0.f;

    uint2 a_cur[4], b_cur[4], a_nxt[4], b_nxt[4];
    a_cur[0] = *(const uint2*)(Arow0);
    a_cur[1] = *(const uint2*)(Arow1);
    a_cur[2] = *(const uint2*)(Arow2);
    a_cur[3] = *(const uint2*)(Arow3);
    #pragma unroll
    for (int nt = 0; nt < 4; nt++)
        b_cur[nt] = *(const uint2*)(Brow0 + nt * 8 * AST);

    #pragma unroll
    for (int ks = 0; ks < 16; ks++) {
        if (ks < 15) {
            int off = (ks + 1) * 8;
            a_nxt[0] = *(const uint2*)(Arow0 + off);
            a_nxt[1] = *(const uint2*)(Arow1 + off);
            a_nxt[2] = *(const uint2*)(Arow2 + off);
            a_nxt[3] = *(const uint2*)(Arow3 + off);
            #pragma unroll
            for (int nt = 0; nt < 4; nt++)
                b_nxt[nt] = *(const uint2*)(Brow0 + nt * 8 * AST + off);
        }
        #pragma unroll
        for (int nt = 0; nt < 4; nt++) {
            mma_tf32(acc[0][nt][0], acc[0][nt][1], acc[0][nt][2], acc[0][nt][3],
                     a_cur[0].x, a_cur[1].x, a_cur[0].y, a_cur[1].y,
                     b_cur[nt].x, b_cur[nt].y);
            mma_tf32(acc[1][nt][0], acc[1][nt][1], acc[1][nt][2], acc[1][nt][3],
                     a_cur[2].x, a_cur[3].x, a_cur[2].y, a_cur[3].y,
                     b_cur[nt].x, b_cur[nt].y);
        }
        #pragma unroll
        for (int j = 0; j < 4; j++) { a_cur[j] = a_nxt[j]; b_cur[j] = b_nxt[j]; }
    }

    #pragma unroll
    for (int nt = 0; nt < 4; nt++) {
        int col = wn + nt * 8 + 2 * qid;
        float bv0 = __ldg(&bias[col]);
        float bv1 = __ldg(&bias[col + 1]);
        float s0 = 0.f, s1 = 0.f, q0 = 0.f, q1 = 0.f;
        #pragma unroll
        for (int mt = 0; mt < 2; mt++) {
            int r = row0 + wm + mt * 16 + grp;
            float v0 = acc[mt][nt][0] + bv0;
            float v1 = acc[mt][nt][1] + bv1;
            float v2 = acc[mt][nt][2] + bv0;
            float v3 = acc[mt][nt][3] + bv1;
            if (RELU) {
                v0 = fmaxf(v0, 0.f); v1 = fmaxf(v1, 0.f);
                v2 = fmaxf(v2, 0.f); v3 = fmaxf(v3, 0.f);
            }
            if (r < NN) {
                *(float2*)(Cout + (size_t)r * DD + col) = make_float2(v0, v1);
                if (STATS) { s0 += v0; s1 += v1; q0 += v0 * v0; q1 += v1 * v1; }
            }
            if (r + 8 < NN) {
                *(float2*)(Cout + (size_t)(r + 8) * DD + col) = make_float2(v2, v3);
                if (STATS) { s0 += v2; s1 += v3; q0 += v2 * v2; q1 += v3 * v3; }
            }
        }
        if (STATS) {
            #pragma unroll
            for (int m = 4; m < 32; m <<= 1) {
                s0 += __shfl_xor_sync(0xFFFFFFFF, s0, m);
                s1 += __shfl_xor_sync(0xFFFFFFFF, s1, m);
                q0 += __shfl_xor_sync(0xFFFFFFFF, q0, m);
                q1 += __shfl_xor_sync(0xFFFFFFFF, q1, m);
            }
            if (grp == 0) {
                atomicAdd(&g_sum[l * DD + col], s0);
                atomicAdd(&g_sum[l * DD + col + 1], s1);
                atomicAdd(&g_sqs[l * DD + col], q0);
                atomicAdd(&g_sqs[l * DD + col + 1], q1);
            }
        }
    }
}

// ---------------- BN finalize + relu + pool (block-local pooling) ----------------
__global__ void bn_relu_pool_kernel(const float* __restrict__ gamma,
                                    const float* __restrict__ beta, int l) {
    __shared__ float s_sc[DD], s_sf[DD];
    __shared__ float4 buf[256];
    int tid = threadIdx.x;
    if (tid < DD) {
        float mean = g_sum[l * DD + tid] * (1.0f / NN);
        float var = g_sqs[l * DD + tid] * (1.0f / NN) - mean * mean;
        float sc = __ldg(&gamma[l * DD + tid]) * rsqrtf(var + 1e-5f);
        s_sc[tid] = sc;
        s_sf[tid] = __ldg(&beta[l * DD + tid]) - mean * sc;
    }
    __syncthreads();
    int i = blockIdx.x * 256 + tid;
    int r = i >> 5;
    int c4 = (i & 31) << 2;
    float4 z = ((const float4*)g_Z)[i];
    float4 hv;
    hv.x = fmaxf(z.x * s_sc[c4]     + s_sf[c4],     0.f);
    hv.y = fmaxf(z.y * s_sc[c4 + 1] + s_sf[c4 + 1], 0.f);
    hv.z = fmaxf(z.z * s_sc[c4 + 2] + s_sf[c4 + 2], 0.f);
    hv.w = fmaxf(z.w * s_sc[c4 + 3] + s_sf[c4 + 3], 0.f);
    ((float4*)g_H)[i] = hv;

    int r0 = (blockIdx.x * 256) >> 5;
    int bfirst = __ldg(&g_batch[r0]);
    int blast  = __ldg(&g_batch[r0 + 7]);
    if (bfirst == blast) {
        buf[tid] = hv;
        __syncthreads();
        if (tid < 128) {
            buf[tid].x += buf[tid + 128].x; buf[tid].y += buf[tid + 128].y;
            buf[tid].z += buf[tid + 128].z; buf[tid].w += buf[tid + 128].w;
        }
        __syncthreads();
        if (tid < 64) {
            buf[tid].x += buf[tid + 64].x; buf[tid].y += buf[tid + 64].y;
            buf[tid].z += buf[tid + 64].z; buf[tid].w += buf[tid + 64].w;
        }
        __syncthreads();
        if (tid < 32) {
            float4 v = buf[tid];
            float4 w = buf[tid + 32];
            v.x += w.x; v.y += w.y; v.z += w.z; v.w += w.w;
            red_add_v4(&g_pool[(size_t)bfirst * (NL * DD) + l * DD + (tid << 2)], v);
        }
    } else {
        int b = __ldg(&g_batch[r]);
        red_add_v4(&g_pool[(size_t)b * (NL * DD) + l * DD + c4], hv);
    }
}

// ---------------- final linear ----------------
__global__ void final_kernel(const float* __restrict__ Wlin,
                             const float* __restrict__ blin,
                             float* __restrict__ out) {
    int t = blockIdx.x * blockDim.x + threadIdx.x;
    if (t >= NG * NC) return;
    int gph = t / NC, c = t % NC;
    float acc = __ldg(&blin[c]);
    const float* prow = &g_pool[(size_t)gph * (NL * DD)];
    #pragma unroll 8
    for (int k = 0; k < NL * DD; k++)
        acc += __ldg(&prow[k]) * __ldg(&Wlin[k * NC + c]);
    out[gph * NC + c] = acc;
}

extern "C" void kernel_launch(void* const* d_in, const int* in_sizes, int n_in,
                              void* d_out, int out_size) {
    const float* x     = (const float*)d_in[0];
    const int*   ei32  = (const int*)d_in[1];
    const int*   b32   = (const int*)d_in[2];
    const float* W1    = (const float*)d_in[3];
    const float* b1    = (const float*)d_in[4];
    const float* W2    = (const float*)d_in[5];
    const float* b2    = (const float*)d_in[6];
    const float* eps   = (const float*)d_in[7];
    const float* gamma = (const float*)d_in[8];
    const float* beta  = (const float*)d_in[9];
    const float* Wlin  = (const float*)d_in[10];
    const float* blin  = (const float*)d_in[11];
    float* out = (float*)d_out;

    cudaFuncSetAttribute(gemm_mma_kernel<true, false>,
                         cudaFuncAttributeMaxDynamicSharedMemorySize, SMEM_GEMM);
    cudaFuncSetAttribute(gemm_mma_kernel<false, true>,
                         cudaFuncAttributeMaxDynamicSharedMemorySize, SMEM_GEMM);

    // init via memset nodes (not kernel launches)
    void *p_mode_ei, *p_mode_b, *p_deg, *p_pool, *p_sum, *p_sqs, *p_bar;
    cudaGetSymbolAddress(&p_mode_ei, g_mode_ei);
    cudaGetSymbolAddress(&p_mode_b,  g_mode_b);
    cudaGetSymbolAddress(&p_deg,     g_deg);
    cudaGetSymbolAddress(&p_pool,    g_pool);
    cudaGetSymbolAddress(&p_sum,     g_sum);
    cudaGetSymbolAddress(&p_sqs,     g_sqs);
    cudaGetSymbolAddress(&p_bar,     g_bar);
    cudaMemsetAsync(p_mode_ei, 1, 4);
    cudaMemsetAsync(p_mode_b,  1, 4);
    cudaMemsetAsync(p_bar,     0, 3 * sizeof(int));
    cudaMemsetAsync(p_deg,  0, NN * sizeof(int));
    cudaMemsetAsync(p_pool, 0, NG * NL * DD * sizeof(float));
    cudaMemsetAsync(p_sum,  0, NL * DD * sizeof(float));
    cudaMemsetAsync(p_sqs,  0, NL * DD * sizeof(float));

    preamble_kernel<<<148, 256>>>(ei32, b32, W1, W2);               // launch 0

    int zgrid = NN * DD / 4 / 256;
    int agrid = (NN * 32 + 255) / 256;

    uint32_t* wt_base;
    cudaGetSymbolAddress((void**)&wt_base, g_Wt);
    float *zb, *tb;
    cudaGetSymbolAddress((void**)&zb, g_Z);
    cudaGetSymbolAddress((void**)&tb, g_T);

    for (int l = 0; l < NL; l++) {
        agg_kernel<<<agrid, 256>>>(x, eps, l);                      // launch 1 (l=0)
        gemm_mma_kernel<true, false><<<NTILES, 256, SMEM_GEMM>>>(
            wt_base + (size_t)l * DD * AST, b1 + l * DD, zb, tb, l);      // launch 2
        gemm_mma_kernel<false, true><<<NTILES, 256, SMEM_GEMM>>>(
            wt_base + (size_t)(NL + l) * DD * AST, b2 + l * DD, tb, zb, l); // launch 3 -> ncu
        bn_relu_pool_kernel<<<zgrid, 256>>>(gamma, beta, l);
    }
    final_kernel<<<(NG * NC + 255) / 256, 256>>>(Wlin, blin, out);
}

// round 14
// speedup vs baseline: 1.8482x; 1.0618x over previous
#include <cuda_runtime.h>
#include <cstdint>

#define NN 50000
#define NE 600000
#define DD 128
#define NL 4
#define NG 512
#define NC 10
#define AST 136        // A smem stride (floats); 136 mod 32 = 8 -> LDS.64 conflict-free
#define BST 40         // B chunk smem stride (floats); 40 mod 32 = 8 -> conflict-free
#define MT 64          // GEMM M tile
#define NTILES ((NN + MT - 1) / MT)   // 782

// ---- scratch (device globals: allocation-free) ----
__device__ float g_H[NN * DD];
__device__ float g_Z[NN * DD];
__device__ float g_T[NN * DD];
__device__ float g_sum[NL * DD];
__device__ float g_sqs[NL * DD];
__device__ float g_pool[NG * NL * DD];
__device__ uint32_t g_Wt[2][NL][DD * AST];   // transposed, pair-permuted, tf32

__device__ int g_src[NE];
__device__ int g_dst[NE];
__device__ int g_batch[NN];
__device__ int g_deg[NN];
__device__ int g_ptr[NN + 1];
__device__ int g_off[NN];
__device__ int g_csr_src[NE];
__device__ int g_mode_ei;
__device__ int g_mode_b;
__device__ int g_bar[3];

__device__ __forceinline__ void red_add_v4(float* p, float4 v) {
    asm volatile("red.global.add.v4.f32 [%0], {%1, %2, %3, %4};"
                 :: "l"(p), "f"(v.x), "f"(v.y), "f"(v.z), "f"(v.w)
                 : "memory");
}
__device__ __forceinline__ uint32_t f2tf32(float f) {
    uint32_t u;
    asm("cvt.rna.tf32.f32 %0, %1;" : "=r"(u) : "f"(f));
    return u;
}
__device__ __forceinline__ void mma_tf32(float& c0, float& c1, float& c2, float& c3,
                                         uint32_t a0, uint32_t a1, uint32_t a2, uint32_t a3,
                                         uint32_t b0, uint32_t b1) {
    asm volatile(
        "mma.sync.aligned.m16n8k8.row.col.f32.tf32.tf32.f32 "
        "{%0,%1,%2,%3}, {%4,%5,%6,%7}, {%8,%9}, {%0,%1,%2,%3};"
        : "+f"(c0), "+f"(c1), "+f"(c2), "+f"(c3)
        : "r"(a0), "r"(a1), "r"(a2), "r"(a3), "r"(b0), "r"(b1));
}
__device__ __forceinline__ int kperm(int k) {
    return (k & ~7) + ((k & 3) << 1) + ((k >> 2) & 1);
}
__device__ __forceinline__ void cp_async16(uint32_t dst, const void* src) {
    asm volatile("cp.async.cg.shared.global [%0], [%1], 16;"
                 :: "r"(dst), "l"(src) : "memory");
}
__device__ __forceinline__ void cp_commit() {
    asm volatile("cp.async.commit_group;" ::: "memory");
}
template<int N> __device__ __forceinline__ void cp_wait() {
    asm volatile("cp.async.wait_group %0;" :: "n"(N) : "memory");
}
__device__ __forceinline__ void pair_bar(int id) {
    asm volatile("bar.sync %0, %1;" :: "r"(id), "r"(64) : "memory");
}

// ---------------- single persistent preamble kernel (148 CTAs) ----------------
__device__ __forceinline__ void gbarrier(int idx) {
    __syncthreads();
    __threadfence();
    if (threadIdx.x == 0) {
        atomicAdd(&g_bar[idx], 1);
        while (atomicAdd(&g_bar[idx], 0) < 148) __nanosleep(64);
    }
    __syncthreads();
}

__global__ __launch_bounds__(256)
void preamble_kernel(const int* __restrict__ ei32,
                     const int* __restrict__ b32,
                     const float* __restrict__ W1,
                     const float* __restrict__ W2) {
    int tid = threadIdx.x;
    const int STRIDE = 148 * 256;

    int nz_ei = 0, nz_b = 0;
    for (int i = blockIdx.x * 256 + tid; i < NE; i += STRIDE) {
        if (ei32[2 * i + 1] != 0) nz_ei = 1;
        if (2 * i + 1 < NN && b32[2 * i + 1] != 0) nz_b = 1;
    }
    int any_ei = __syncthreads_or(nz_ei);
    int any_b  = __syncthreads_or(nz_b);
    if (tid == 0) {
        if (any_ei) atomicExch(&g_mode_ei, 0);
        if (any_b)  atomicExch(&g_mode_b, 0);
    }
    gbarrier(0);

    int m_ei = atomicAdd(&g_mode_ei, 0);
    int m_b  = atomicAdd(&g_mode_b, 0);
    for (int i = blockIdx.x * 256 + tid; i < NE; i += STRIDE) {
        int s = m_ei ? ei32[2 * i]        : ei32[i];
        int d = m_ei ? ei32[2 * (NE + i)] : ei32[NE + i];
        g_src[i] = s;
        g_dst[i] = d;
        atomicAdd(&g_deg[d], 1);
        if (i < NN) g_batch[i] = m_b ? b32[2 * i] : b32[i];
    }
    gbarrier(1);

    if (blockIdx.x == 0) {
        __shared__ int sh[256];
        const int CH = (NN + 255) / 256;
        int b0 = tid * CH, b1 = min(b0 + CH, NN);
        int s = 0;
        for (int i = b0; i < b1; i++) s += g_deg[i];
        sh[tid] = s;
        __syncthreads();
        #pragma unroll
        for (int off = 1; off < 256; off <<= 1) {
            int v = (tid >= off) ? sh[tid - off] : 0;
            __syncthreads();
            sh[tid] += v;
            __syncthreads();
        }
        int run = (tid > 0) ? sh[tid - 1] : 0;
        for (int i = b0; i < b1; i++) {
            g_ptr[i] = run; g_off[i] = run;
            run += g_deg[i];
        }
        if (tid == 0) g_ptr[NN] = NE;
    } else {
        for (int i = (blockIdx.x - 1) * 256 + tid; i < 2 * NL * DD * DD;
             i += 147 * 256) {
            int which = i / (NL * DD * DD);
            int r = i % (NL * DD * DD);
            int l = r / (DD * DD);
            int e = r % (DD * DD);
            int k = e / DD, n = e % DD;
            const float* w = which ? W2 : W1;
            g_Wt[which][l][n * AST + kperm(k)] = f2tf32(w[l * DD * DD + k * DD + n]);
        }
    }
    gbarrier(2);

    for (int i = blockIdx.x * 256 + tid; i < NE; i += STRIDE) {
        int d = g_dst[i];
        int pos = atomicAdd(&g_off[d], 1);
        g_csr_src[pos] = g_src[i];
    }
}

// ---------------- fused (1+eps)*h + CSR neighbor-sum (high occupancy) ----------------
__global__ void agg_kernel(const float* __restrict__ x,
                           const float* __restrict__ eps, int l) {
    int warp = (blockIdx.x * blockDim.x + threadIdx.x) >> 5;
    if (warp >= NN) return;
    int lane = threadIdx.x & 31;
    const float* h = l ? g_H : x;
    const float4* hv = (const float4*)h;
    float e = 1.0f + __ldg(&eps[l]);
    float4 a = hv[warp * 32 + lane];
    float4 acc = make_float4(a.x * e, a.y * e, a.z * e, a.w * e);
    int p = __ldg(&g_ptr[warp]);
    int p1 = __ldg(&g_ptr[warp + 1]);
    for (; p + 4 <= p1; p += 4) {
        int s0 = __ldg(&g_csr_src[p]);
        int s1 = __ldg(&g_csr_src[p + 1]);
        int s2 = __ldg(&g_csr_src[p + 2]);
        int s3 = __ldg(&g_csr_src[p + 3]);
        float4 v0 = __ldg(&hv[s0 * 32 + lane]);
        float4 v1 = __ldg(&hv[s1 * 32 + lane]);
        float4 v2 = __ldg(&hv[s2 * 32 + lane]);
        float4 v3 = __ldg(&hv[s3 * 32 + lane]);
        acc.x += v0.x + v1.x + v2.x + v3.x;
        acc.y += v0.y + v1.y + v2.y + v3.y;
        acc.z += v0.z + v1.z + v2.z + v3.z;
        acc.w += v0.w + v1.w + v2.w + v3.w;
    }
    for (; p < p1; p++) {
        int s = __ldg(&g_csr_src[p]);
        float4 v = __ldg(&hv[s * 32 + lane]);
        acc.x += v.x; acc.y += v.y; acc.z += v.z; acc.w += v.w;
    }
    ((float4*)g_Z)[warp * 32 + lane] = acc;
}

// ---------------- mma.sync tf32 GEMM: cp.async chunked-B double buffer,
// 3 CTAs/SM. A resident [64][AST]; B in 4 k-chunks of 32 cols, [2][128][BST]. --------
#define SMEM_GEMM ((MT * AST + 2 * DD * BST) * 4)   // 75776 bytes

template<bool RELU, bool STATS>
__global__ __launch_bounds__(256, 3)
void gemm_mma_kernel(const uint32_t* __restrict__ Wt,
                     const float* __restrict__ bias,
                     const float* __restrict__ Ain,
                     float* __restrict__ Cout,
                     int l) {
    extern __shared__ __align__(16) uint32_t smem[];
    uint32_t* As = smem;                       // [64][AST]
    uint32_t* Bs[2] = { smem + MT * AST, smem + MT * AST + DD * BST };
    int tid = threadIdx.x;
    int row0 = blockIdx.x * MT;
    int wid = tid >> 5, lane = tid & 31;
    int wm = (wid & 1) * 32;
    int wn = (wid >> 1) * 32;
    int grp = lane >> 2, qid = lane & 3;
    int pair = 1 + (wid >> 1);        // named barrier id per wn-pair
    int half = (wid & 1) * 16;        // this warp copies rows [wn+half, wn+half+16)

    // issue B chunk c into buffer: 16 rows x 32 floats, 4x 16B per lane
    auto issue_b = [&](int c, uint32_t* Bb) {
        #pragma unroll
        for (int t = 0; t < 4; t++) {
            int idx = t * 32 + lane;
            int rloc = idx >> 3;      // 0..15
            int g16 = idx & 7;        // 16B granule in 32-float chunk
            int row = wn + half + rloc;
            const uint32_t* src = Wt + row * AST + c * 32 + g16 * 4;
            uint32_t dst = (uint32_t)__cvta_generic_to_shared(Bb + row * BST + g16 * 4);
            cp_async16(dst, src);
        }
        cp_commit();
    };

    issue_b(0, Bs[0]);
    issue_b(1, Bs[1]);

    // A tile: LDG + tf32 cvt + pair-permute STS
    #pragma unroll 2
    for (int i = tid; i < MT * 32; i += 256) {
        int m = i >> 5;
        int k4 = i & 31;
        int gm = row0 + m;
        float4 v = make_float4(0.f, 0.f, 0.f, 0.f);
        if (gm < NN) v = __ldg(&((const float4*)(Ain + (size_t)gm * DD))[k4]);
        uint32_t* p = &As[m * AST + (k4 >> 1) * 8 + (k4 & 1)];
        p[0] = f2tf32(v.x); p[2] = f2tf32(v.y);
        p[4] = f2tf32(v.z); p[6] = f2tf32(v.w);
    }
    __syncthreads();

    const uint32_t* Arow0 = &As[(wm + grp) * AST + qid * 2];
    const uint32_t* Arow1 = Arow0 + 8 * AST;
    const uint32_t* Arow2 = Arow0 + 16 * AST;
    const uint32_t* Arow3 = Arow0 + 24 * AST;

    float acc[2][4][4];
    #pragma unroll
    for (int i = 0; i < 2; i++)
        #pragma unroll
        for (int j = 0; j < 4; j++)
            #pragma unroll
            for (int q = 0; q < 4; q++) acc[i][j][q] = 0.f;

    #pragma unroll
    for (int c = 0; c < 4; c++) {
        if (c < 3) cp_wait<1>(); else cp_wait<0>();
        pair_bar(pair);               // both halves of this pair's chunk present

        const uint32_t* Brow = &Bs[c & 1][(wn + grp) * BST + qid * 2];
        #pragma unroll
        for (int j = 0; j < 4; j++) {
            int aoff = (c * 4 + j) * 8;
            uint2 a0 = *(const uint2*)(Arow0 + aoff);
            uint2 a1 = *(const uint2*)(Arow1 + aoff);
            uint2 a2 = *(const uint2*)(Arow2 + aoff);
            uint2 a3 = *(const uint2*)(Arow3 + aoff);
            #pragma unroll
            for (int nt = 0; nt < 4; nt++) {
                uint2 b = *(const uint2*)(Brow + nt * 8 * BST + j * 8);
                mma_tf32(acc[0][nt][0], acc[0][nt][1], acc[0][nt][2], acc[0][nt][3],
                         a0.x, a1.x, a0.y, a1.y, b.x, b.y);
                mma_tf32(acc[1][nt][0], acc[1][nt][1], acc[1][nt][2], acc[1][nt][3],
                         a2.x, a3.x, a2.y, a3.y, b.x, b.y);
            }
        }

        if (c < 2) {
            pair_bar(pair);           // pair done reading buffer (c&1) before refill
            issue_b(c + 2, Bs[c & 1]);
        }
    }

    #pragma unroll
    for (int nt = 0; nt < 4; nt++) {
        int col = wn + nt * 8 + 2 * qid;
        float bv0 = __ldg(&bias[col]);
        float bv1 = __ldg(&bias[col + 1]);
        float s0 = 0.f, s1 = 0.f, q0 = 0.f, q1 = 0.f;
        #pragma unroll
        for (int mt = 0; mt < 2; mt++) {
            int r = row0 + wm + mt * 16 + grp;
            float v0 = acc[mt][nt][0] + bv0;
            float v1 = acc[mt][nt][1] + bv1;
            float v2 = acc[mt][nt][2] + bv0;
            float v3 = acc[mt][nt][3] + bv1;
            if (RELU) {
                v0 = fmaxf(v0, 0.f); v1 = fmaxf(v1, 0.f);
                v2 = fmaxf(v2, 0.f); v3 = fmaxf(v3, 0.f);
            }
            if (r < NN) {
                *(float2*)(Cout + (size_t)r * DD + col) = make_float2(v0, v1);
                if (STATS) { s0 += v0; s1 += v1; q0 += v0 * v0; q1 += v1 * v1; }
            }
            if (r + 8 < NN) {
                *(float2*)(Cout + (size_t)(r + 8) * DD + col) = make_float2(v2, v3);
                if (STATS) { s0 += v2; s1 += v3; q0 += v2 * v2; q1 += v3 * v3; }
            }
        }
        if (STATS) {
            #pragma unroll
            for (int m = 4; m < 32; m <<= 1) {
                s0 += __shfl_xor_sync(0xFFFFFFFF, s0, m);
                s1 += __shfl_xor_sync(0xFFFFFFFF, s1, m);
                q0 += __shfl_xor_sync(0xFFFFFFFF, q0, m);
                q1 += __shfl_xor_sync(0xFFFFFFFF, q1, m);
            }
            if (grp == 0) {
                atomicAdd(&g_sum[l * DD + col], s0);
                atomicAdd(&g_sum[l * DD + col + 1], s1);
                atomicAdd(&g_sqs[l * DD + col], q0);
                atomicAdd(&g_sqs[l * DD + col + 1], q1);
            }
        }
    }
}

// ---------------- BN finalize + relu + pool (block-local pooling) ----------------
__global__ void bn_relu_pool_kernel(const float* __restrict__ gamma,
                                    const float* __restrict__ beta, int l) {
    __shared__ float s_sc[DD], s_sf[DD];
    __shared__ float4 buf[256];
    int tid = threadIdx.x;
    if (tid < DD) {
        float mean = g_sum[l * DD + tid] * (1.0f / NN);
        float var = g_sqs[l * DD + tid] * (1.0f / NN) - mean * mean;
        float sc = __ldg(&gamma[l * DD + tid]) * rsqrtf(var + 1e-5f);
        s_sc[tid] = sc;
        s_sf[tid] = __ldg(&beta[l * DD + tid]) - mean * sc;
    }
    __syncthreads();
    int i = blockIdx.x * 256 + tid;
    int r = i >> 5;
    int c4 = (i & 31) << 2;
    float4 z = ((const float4*)g_Z)[i];
    float4 hv;
    hv.x = fmaxf(z.x * s_sc[c4]     + s_sf[c4],     0.f);
    hv.y = fmaxf(z.y * s_sc[c4 + 1] + s_sf[c4 + 1], 0.f);
    hv.z = fmaxf(z.z * s_sc[c4 + 2] + s_sf[c4 + 2], 0.f);
    hv.w = fmaxf(z.w * s_sc[c4 + 3] + s_sf[c4 + 3], 0.f);
    ((float4*)g_H)[i] = hv;

    int r0 = (blockIdx.x * 256) >> 5;
    int bfirst = __ldg(&g_batch[r0]);
    int blast  = __ldg(&g_batch[r0 + 7]);
    if (bfirst == blast) {
        buf[tid] = hv;
        __syncthreads();
        if (tid < 128) {
            buf[tid].x += buf[tid + 128].x; buf[tid].y += buf[tid + 128].y;
            buf[tid].z += buf[tid + 128].z; buf[tid].w += buf[tid + 128].w;
        }
        __syncthreads();
        if (tid < 64) {
            buf[tid].x += buf[tid + 64].x; buf[tid].y += buf[tid + 64].y;
            buf[tid].z += buf[tid + 64].z; buf[tid].w += buf[tid + 64].w;
        }
        __syncthreads();
        if (tid < 32) {
            float4 v = buf[tid];
            float4 w = buf[tid + 32];
            v.x += w.x; v.y += w.y; v.z += w.z; v.w += w.w;
            red_add_v4(&g_pool[(size_t)bfirst * (NL * DD) + l * DD + (tid << 2)], v);
        }
    } else {
        int b = __ldg(&g_batch[r]);
        red_add_v4(&g_pool[(size_t)b * (NL * DD) + l * DD + c4], hv);
    }
}

// ---------------- final linear ----------------
__global__ void final_kernel(const float* __restrict__ Wlin,
                             const float* __restrict__ blin,
                             float* __restrict__ out) {
    int t = blockIdx.x * blockDim.x + threadIdx.x;
    if (t >= NG * NC) return;
    int gph = t / NC, c = t % NC;
    float acc = __ldg(&blin[c]);
    const float* prow = &g_pool[(size_t)gph * (NL * DD)];
    #pragma unroll 8
    for (int k = 0; k < NL * DD; k++)
        acc += __ldg(&prow[k]) * __ldg(&Wlin[k * NC + c]);
    out[gph * NC + c] = acc;
}

extern "C" void kernel_launch(void* const* d_in, const int* in_sizes, int n_in,
                              void* d_out, int out_size) {
    const float* x     = (const float*)d_in[0];
    const int*   ei32  = (const int*)d_in[1];
    const int*   b32   = (const int*)d_in[2];
    const float* W1    = (const float*)d_in[3];
    const float* b1    = (const float*)d_in[4];
    const float* W2    = (const float*)d_in[5];
    const float* b2    = (const float*)d_in[6];
    const float* eps   = (const float*)d_in[7];
    const float* gamma = (const float*)d_in[8];
    const float* beta  = (const float*)d_in[9];
    const float* Wlin  = (const float*)d_in[10];
    const float* blin  = (const float*)d_in[11];
    float* out = (float*)d_out;

    cudaFuncSetAttribute(gemm_mma_kernel<true, false>,
                         cudaFuncAttributeMaxDynamicSharedMemorySize, SMEM_GEMM);
    cudaFuncSetAttribute(gemm_mma_kernel<false, true>,
                         cudaFuncAttributeMaxDynamicSharedMemorySize, SMEM_GEMM);

    void *p_mode_ei, *p_mode_b, *p_deg, *p_pool, *p_sum, *p_sqs, *p_bar;
    cudaGetSymbolAddress(&p_mode_ei, g_mode_ei);
    cudaGetSymbolAddress(&p_mode_b,  g_mode_b);
    cudaGetSymbolAddress(&p_deg,     g_deg);
    cudaGetSymbolAddress(&p_pool,    g_pool);
    cudaGetSymbolAddress(&p_sum,     g_sum);
    cudaGetSymbolAddress(&p_sqs,     g_sqs);
    cudaGetSymbolAddress(&p_bar,     g_bar);
    cudaMemsetAsync(p_mode_ei, 1, 4);
    cudaMemsetAsync(p_mode_b,  1, 4);
    cudaMemsetAsync(p_bar,     0, 3 * sizeof(int));
    cudaMemsetAsync(p_deg,  0, NN * sizeof(int));
    cudaMemsetAsync(p_pool, 0, NG * NL * DD * sizeof(float));
    cudaMemsetAsync(p_sum,  0, NL * DD * sizeof(float));
    cudaMemsetAsync(p_sqs,  0, NL * DD * sizeof(float));

    preamble_kernel<<<148, 256>>>(ei32, b32, W1, W2);               // launch 0

    int zgrid = NN * DD / 4 / 256;
    int agrid = (NN * 32 + 255) / 256;

    uint32_t* wt_base;
    cudaGetSymbolAddress((void**)&wt_base, g_Wt);
    float *zb, *tb;
    cudaGetSymbolAddress((void**)&zb, g_Z);
    cudaGetSymbolAddress((void**)&tb, g_T);

    for (int l = 0; l < NL; l++) {
        agg_kernel<<<agrid, 256>>>(x, eps, l);                      // launch 1 (l=0)
        gemm_mma_kernel<true, false><<<NTILES, 256, SMEM_GEMM>>>(
            wt_base + (size_t)l * DD * AST, b1 + l * DD, zb, tb, l);      // launch 2
        gemm_mma_kernel<false, true><<<NTILES, 256, SMEM_GEMM>>>(
            wt_base + (size_t)(NL + l) * DD * AST, b2 + l * DD, tb, zb, l); // launch 3 -> ncu
        bn_relu_pool_kernel<<<zgrid, 256>>>(gamma, beta, l);
    }
    final_kernel<<<(NG * NC + 255) / 256, 256>>>(Wlin, blin, out);
}

// round 16
// speedup vs baseline: 1.9103x; 1.0336x over previous
#include <cuda_runtime.h>
#include <cstdint>

#define NN 50000
#define NE 600000
#define DD 128
#define NL 4
#define NG 512
#define NC 10
#define AST 136        // B source stride in g_Wt (floats)
#define ASTN 132       // A smem stride (floats); 132 mod 32 = 4 -> LDS.32 conflict-free
#define BST 40         // B chunk smem stride (floats); 40 mod 32 = 8 -> LDS.64 conflict-free
#define MT 64          // GEMM M tile
#define NTILES ((NN + MT - 1) / MT)   // 782

// ---- scratch (device globals: allocation-free) ----
__device__ float g_H[NN * DD];
__device__ float g_Z[NN * DD];
__device__ float g_T[NN * DD];
__device__ float g_sum[NL * DD];
__device__ float g_sqs[NL * DD];
__device__ float g_pool[NG * NL * DD];
__device__ uint32_t g_Wt[2][NL][DD * AST];   // transposed, pair-permuted, tf32(RNA)

__device__ int g_src[NE];
__device__ int g_dst[NE];
__device__ int g_batch[NN];
__device__ int g_deg[NN];
__device__ int g_ptr[NN + 1];
__device__ int g_off[NN];
__device__ int g_csr_src[NE];
__device__ int g_not64_ei;    // 0 = int64 source, nonzero = int32 (zero-init via memset)
__device__ int g_not64_b;
__device__ int g_bar[3];

__device__ __forceinline__ void red_add_v4(float* p, float4 v) {
    asm volatile("red.global.add.v4.f32 [%0], {%1, %2, %3, %4};"
                 :: "l"(p), "f"(v.x), "f"(v.y), "f"(v.z), "f"(v.w)
                 : "memory");
}
__device__ __forceinline__ uint32_t f2tf32(float f) {
    uint32_t u;
    asm("cvt.rna.tf32.f32 %0, %1;" : "=r"(u) : "f"(f));
    return u;
}
__device__ __forceinline__ void mma_tf32(float& c0, float& c1, float& c2, float& c3,
                                         uint32_t a0, uint32_t a1, uint32_t a2, uint32_t a3,
                                         uint32_t b0, uint32_t b1) {
    asm volatile(
        "mma.sync.aligned.m16n8k8.row.col.f32.tf32.tf32.f32 "
        "{%0,%1,%2,%3}, {%4,%5,%6,%7}, {%8,%9}, {%0,%1,%2,%3};"
        : "+f"(c0), "+f"(c1), "+f"(c2), "+f"(c3)
        : "r"(a0), "r"(a1), "r"(a2), "r"(a3), "r"(b0), "r"(b1));
}
__device__ __forceinline__ int kperm(int k) {
    return (k & ~7) + ((k & 3) << 1) + ((k >> 2) & 1);
}
__device__ __forceinline__ void cp_async16(uint32_t dst, const void* src) {
    asm volatile("cp.async.cg.shared.global [%0], [%1], 16;"
                 :: "r"(dst), "l"(src) : "memory");
}
__device__ __forceinline__ void cp_commit() {
    asm volatile("cp.async.commit_group;" ::: "memory");
}
template<int N> __device__ __forceinline__ void cp_wait() {
    asm volatile("cp.async.wait_group %0;" :: "n"(N) : "memory");
}

// ---------------- single persistent preamble kernel (148 CTAs) ----------------
__device__ __forceinline__ void gbarrier(int idx) {
    __syncthreads();
    __threadfence();
    if (threadIdx.x == 0) {
        atomicAdd(&g_bar[idx], 1);
        while (atomicAdd(&g_bar[idx], 0) < 148) __nanosleep(64);
    }
    __syncthreads();
}

__global__ __launch_bounds__(256)
void preamble_kernel(const int* __restrict__ ei32,
                     const int* __restrict__ b32,
                     const float* __restrict__ W1,
                     const float* __restrict__ W2) {
    int tid = threadIdx.x;
    const int STRIDE = 148 * 256;

    // phase 1: dtype detection (block-reduced; flags zero-initialized)
    int nz_ei = 0, nz_b = 0;
    for (int i = blockIdx.x * 256 + tid; i < NE; i += STRIDE) {
        if (ei32[2 * i + 1] != 0) nz_ei = 1;
        if (2 * i + 1 < NN && b32[2 * i + 1] != 0) nz_b = 1;
    }
    int any_ei = __syncthreads_or(nz_ei);
    int any_b  = __syncthreads_or(nz_b);
    if (tid == 0) {
        if (any_ei) atomicExch(&g_not64_ei, 1);
        if (any_b)  atomicExch(&g_not64_b, 1);
    }
    gbarrier(0);

    // phase 2: convert + degree histogram
    int is64_ei = (atomicAdd(&g_not64_ei, 0) == 0);
    int is64_b  = (atomicAdd(&g_not64_b, 0) == 0);
    for (int i = blockIdx.x * 256 + tid; i < NE; i += STRIDE) {
        int s = is64_ei ? ei32[2 * i]        : ei32[i];
        int d = is64_ei ? ei32[2 * (NE + i)] : ei32[NE + i];
        g_src[i] = s;
        g_dst[i] = d;
        atomicAdd(&g_deg[d], 1);
        if (i < NN) g_batch[i] = is64_b ? b32[2 * i] : b32[i];
    }
    gbarrier(1);

    // phase 3: block 0 scans degrees; others transpose/tf32-prep weights
    if (blockIdx.x == 0) {
        __shared__ int sh[256];
        const int CH = (NN + 255) / 256;
        int b0 = tid * CH, b1 = min(b0 + CH, NN);
        int s = 0;
        for (int i = b0; i < b1; i++) s += g_deg[i];
        sh[tid] = s;
        __syncthreads();
        #pragma unroll
        for (int off = 1; off < 256; off <<= 1) {
            int v = (tid >= off) ? sh[tid - off] : 0;
            __syncthreads();
            sh[tid] += v;
            __syncthreads();
        }
        int run = (tid > 0) ? sh[tid - 1] : 0;
        for (int i = b0; i < b1; i++) {
            g_ptr[i] = run; g_off[i] = run;
            run += g_deg[i];
        }
        if (tid == 0) g_ptr[NN] = NE;
    } else {
        for (int i = (blockIdx.x - 1) * 256 + tid; i < 2 * NL * DD * DD;
             i += 147 * 256) {
            int which = i / (NL * DD * DD);
            int r = i % (NL * DD * DD);
            int l = r / (DD * DD);
            int e = r % (DD * DD);
            int k = e / DD, n = e % DD;
            const float* w = which ? W2 : W1;
            g_Wt[which][l][n * AST + kperm(k)] = f2tf32(w[l * DD * DD + k * DD + n]);
        }
    }
    gbarrier(2);

    // phase 4: scatter edges into CSR
    for (int i = blockIdx.x * 256 + tid; i < NE; i += STRIDE) {
        int d = g_dst[i];
        int pos = atomicAdd(&g_off[d], 1);
        g_csr_src[pos] = g_src[i];
    }
}

// ---------------- fused (1+eps)*h + CSR neighbor-sum (high occupancy) ----------------
__global__ void agg_kernel(const float* __restrict__ x,
                           const float* __restrict__ eps, int l) {
    int warp = (blockIdx.x * blockDim.x + threadIdx.x) >> 5;
    if (warp >= NN) return;
    int lane = threadIdx.x & 31;
    const float* h = l ? g_H : x;
    const float4* hv = (const float4*)h;
    float e = 1.0f + __ldg(&eps[l]);
    float4 a = hv[warp * 32 + lane];
    float4 acc = make_float4(a.x * e, a.y * e, a.z * e, a.w * e);
    int p = __ldg(&g_ptr[warp]);
    int p1 = __ldg(&g_ptr[warp + 1]);
    for (; p + 4 <= p1; p += 4) {
        int s0 = __ldg(&g_csr_src[p]);
        int s1 = __ldg(&g_csr_src[p + 1]);
        int s2 = __ldg(&g_csr_src[p + 2]);
        int s3 = __ldg(&g_csr_src[p + 3]);
        float4 v0 = __ldg(&hv[s0 * 32 + lane]);
        float4 v1 = __ldg(&hv[s1 * 32 + lane]);
        float4 v2 = __ldg(&hv[s2 * 32 + lane]);
        float4 v3 = __ldg(&hv[s3 * 32 + lane]);
        acc.x += v0.x + v1.x + v2.x + v3.x;
        acc.y += v0.y + v1.y + v2.y + v3.y;
        acc.z += v0.z + v1.z + v2.z + v3.z;
        acc.w += v0.w + v1.w + v2.w + v3.w;
    }
    for (; p < p1; p++) {
        int s = __ldg(&g_csr_src[p]);
        float4 v = __ldg(&hv[s * 32 + lane]);
        acc.x += v.x; acc.y += v.y; acc.z += v.z; acc.w += v.w;
    }
    ((float4*)g_Z)[warp * 32 + lane] = acc;
}

// ---------------- mma.sync tf32 GEMM: fully-async A+B via cp.async k-chunks.
// A natural fp32 (HW truncates to tf32); B pre-permuted RNA tf32. 3 CTAs/SM. --------
#define SMEM_GEMM ((MT * ASTN + 2 * DD * BST) * 4)   // 74752 bytes

template<bool RELU, bool STATS>
__global__ __launch_bounds__(256, 3)
void gemm_mma_kernel(const uint32_t* __restrict__ Wt,
                     const float* __restrict__ bias,
                     const float* __restrict__ Ain,
                     float* __restrict__ Cout,
                     int l) {
    extern __shared__ __align__(16) uint32_t smem[];
    uint32_t* As = smem;                       // [64][ASTN], natural layout, raw fp32
    uint32_t* Bs[2] = { smem + MT * ASTN, smem + MT * ASTN + DD * BST };
    int tid = threadIdx.x;
    int row0 = blockIdx.x * MT;
    int wid = tid >> 5, lane = tid & 31;
    int wm = (wid & 1) * 32;
    int wn = (wid >> 1) * 32;
    int grp = lane >> 2, qid = lane & 3;

    // one commit group = A k-chunk (64 rows x 32 cols) + B k-chunk (128 rows x 32)
    auto issue_group = [&](int c, uint32_t* Bb) {
        #pragma unroll
        for (int t = 0; t < 2; t++) {          // A: 512 granules of 16B
            int idx = t * 256 + tid;
            int m = idx >> 3, j = idx & 7;
            int gm = row0 + m;
            if (gm >= NN) gm = 0;              // clamped rows discarded in epilogue
            const float* src = Ain + (size_t)gm * DD + c * 32 + j * 4;
            uint32_t dst = (uint32_t)__cvta_generic_to_shared(As + m * ASTN + c * 32 + j * 4);
            cp_async16(dst, src);
        }
        #pragma unroll
        for (int t = 0; t < 4; t++) {          // B: 1024 granules of 16B
            int idx = t * 256 + tid;
            int r = idx >> 3, j = idx & 7;
            const uint32_t* src = Wt + r * AST + c * 32 + j * 4;
            uint32_t dst = (uint32_t)__cvta_generic_to_shared(Bb + r * BST + j * 4);
            cp_async16(dst, src);
        }
        cp_commit();
    };

    issue_group(0, Bs[0]);
    issue_group(1, Bs[1]);

    const uint32_t* A0p = &As[(wm + grp) * ASTN];
    const uint32_t* A1p = A0p + 8 * ASTN;
    const uint32_t* A2p = A0p + 16 * ASTN;
    const uint32_t* A3p = A0p + 24 * ASTN;

    float acc[2][4][4];
    #pragma unroll
    for (int i = 0; i < 2; i++)
        #pragma unroll
        for (int j = 0; j < 4; j++)
            #pragma unroll
            for (int q = 0; q < 4; q++) acc[i][j][q] = 0.f;

    #pragma unroll
    for (int c = 0; c < 4; c++) {
        if (c < 3) cp_wait<1>(); else cp_wait<0>();
        __syncthreads();                       // group c visible to all warps

        const uint32_t* Brow = &Bs[c & 1][(wn + grp) * BST + qid * 2];
        #pragma unroll
        for (int j = 0; j < 4; j++) {
            int ka = c * 32 + j * 8 + qid;
            uint32_t a0 = A0p[ka], a0h = A0p[ka + 4];
            uint32_t a1 = A1p[ka], a1h = A1p[ka + 4];
            uint32_t a2 = A2p[ka], a2h = A2p[ka + 4];
            uint32_t a3 = A3p[ka], a3h = A3p[ka + 4];
            #pragma unroll
            for (int nt = 0; nt < 4; nt++) {
                uint2 b = *(const uint2*)(Brow + nt * 8 * BST + j * 8);
                mma_tf32(acc[0][nt][0], acc[0][nt][1], acc[0][nt][2], acc[0][nt][3],
                         a0, a1, a0h, a1h, b.x, b.y);
                mma_tf32(acc[1][nt][0], acc[1][nt][1], acc[1][nt][2], acc[1][nt][3],
                         a2, a3, a2h, a3h, b.x, b.y);
            }
        }

        if (c < 2) {
            __syncthreads();                   // all warps done with B buffer (c&1)
            issue_group(c + 2, Bs[c & 1]);
        }
    }

    #pragma unroll
    for (int nt = 0; nt < 4; nt++) {
        int col = wn + nt * 8 + 2 * qid;
        float bv0 = __ldg(&bias[col]);
        float bv1 = __ldg(&bias[col + 1]);
        float s0 = 0.f, s1 = 0.f, q0 = 0.f, q1 = 0.f;
        #pragma unroll
        for (int mt = 0; mt < 2; mt++) {
            int r = row0 + wm + mt * 16 + grp;
            float v0 = acc[mt][nt][0] + bv0;
            float v1 = acc[mt][nt][1] + bv1;
            float v2 = acc[mt][nt][2] + bv0;
            float v3 = acc[mt][nt][3] + bv1;
            if (RELU) {
                v0 = fmaxf(v0, 0.f); v1 = fmaxf(v1, 0.f);
                v2 = fmaxf(v2, 0.f); v3 = fmaxf(v3, 0.f);
            }
            if (r < NN) {
                *(float2*)(Cout + (size_t)r * DD + col) = make_float2(v0, v1);
                if (STATS) { s0 += v0; s1 += v1; q0 += v0 * v0; q1 += v1 * v1; }
            }
            if (r + 8 < NN) {
                *(float2*)(Cout + (size_t)(r + 8) * DD + col) = make_float2(v2, v3);
                if (STATS) { s0 += v2; s1 += v3; q0 += v2 * v2; q1 += v3 * v3; }
            }
        }
        if (STATS) {
            #pragma unroll
            for (int m = 4; m < 32; m <<= 1) {
                s0 += __shfl_xor_sync(0xFFFFFFFF, s0, m);
                s1 += __shfl_xor_sync(0xFFFFFFFF, s1, m);
                q0 += __shfl_xor_sync(0xFFFFFFFF, q0, m);
                q1 += __shfl_xor_sync(0xFFFFFFFF, q1, m);
            }
            if (grp == 0) {
                atomicAdd(&g_sum[l * DD + col], s0);
                atomicAdd(&g_sum[l * DD + col + 1], s1);
                atomicAdd(&g_sqs[l * DD + col], q0);
                atomicAdd(&g_sqs[l * DD + col + 1], q1);
            }
        }
    }
}

// ---------------- BN finalize + relu + pool (block-local pooling) ----------------
__global__ void bn_relu_pool_kernel(const float* __restrict__ gamma,
                                    const float* __restrict__ beta, int l) {
    __shared__ float s_sc[DD], s_sf[DD];
    __shared__ float4 buf[256];
    int tid = threadIdx.x;
    if (tid < DD) {
        float mean = g_sum[l * DD + tid] * (1.0f / NN);
        float var = g_sqs[l * DD + tid] * (1.0f / NN) - mean * mean;
        float sc = __ldg(&gamma[l * DD + tid]) * rsqrtf(var + 1e-5f);
        s_sc[tid] = sc;
        s_sf[tid] = __ldg(&beta[l * DD + tid]) - mean * sc;
    }
    __syncthreads();
    int i = blockIdx.x * 256 + tid;
    int r = i >> 5;
    int c4 = (i & 31) << 2;
    float4 z = ((const float4*)g_Z)[i];
    float4 hv;
    hv.x = fmaxf(z.x * s_sc[c4]     + s_sf[c4],     0.f);
    hv.y = fmaxf(z.y * s_sc[c4 + 1] + s_sf[c4 + 1], 0.f);
    hv.z = fmaxf(z.z * s_sc[c4 + 2] + s_sf[c4 + 2], 0.f);
    hv.w = fmaxf(z.w * s_sc[c4 + 3] + s_sf[c4 + 3], 0.f);
    ((float4*)g_H)[i] = hv;

    int r0 = (blockIdx.x * 256) >> 5;
    int bfirst = __ldg(&g_batch[r0]);
    int blast  = __ldg(&g_batch[r0 + 7]);
    if (bfirst == blast) {
        buf[tid] = hv;
        __syncthreads();
        if (tid < 128) {
            buf[tid].x += buf[tid + 128].x; buf[tid].y += buf[tid + 128].y;
            buf[tid].z += buf[tid + 128].z; buf[tid].w += buf[tid + 128].w;
        }
        __syncthreads();
        if (tid < 64) {
            buf[tid].x += buf[tid + 64].x; buf[tid].y += buf[tid + 64].y;
            buf[tid].z += buf[tid + 64].z; buf[tid].w += buf[tid + 64].w;
        }
        __syncthreads();
        if (tid < 32) {
            float4 v = buf[tid];
            float4 w = buf[tid + 32];
            v.x += w.x; v.y += w.y; v.z += w.z; v.w += w.w;
            red_add_v4(&g_pool[(size_t)bfirst * (NL * DD) + l * DD + (tid << 2)], v);
        }
    } else {
        int b = __ldg(&g_batch[r]);
        red_add_v4(&g_pool[(size_t)b * (NL * DD) + l * DD + c4], hv);
    }
}

// ---------------- final linear ----------------
__global__ void final_kernel(const float* __restrict__ Wlin,
                             const float* __restrict__ blin,
                             float* __restrict__ out) {
    int t = blockIdx.x * blockDim.x + threadIdx.x;
    if (t >= NG * NC) return;
    int gph = t / NC, c = t % NC;
    float acc = __ldg(&blin[c]);
    const float* prow = &g_pool[(size_t)gph * (NL * DD)];
    #pragma unroll 8
    for (int k = 0; k < NL * DD; k++)
        acc += __ldg(&prow[k]) * __ldg(&Wlin[k * NC + c]);
    out[gph * NC + c] = acc;
}

extern "C" void kernel_launch(void* const* d_in, const int* in_sizes, int n_in,
                              void* d_out, int out_size) {
    const float* x     = (const float*)d_in[0];
    const int*   ei32  = (const int*)d_in[1];
    const int*   b32   = (const int*)d_in[2];
    const float* W1    = (const float*)d_in[3];
    const float* b1    = (const float*)d_in[4];
    const float* W2    = (const float*)d_in[5];
    const float* b2    = (const float*)d_in[6];
    const float* eps   = (const float*)d_in[7];
    const float* gamma = (const float*)d_in[8];
    const float* beta  = (const float*)d_in[9];
    const float* Wlin  = (const float*)d_in[10];
    const float* blin  = (const float*)d_in[11];
    float* out = (float*)d_out;

    cudaFuncSetAttribute(gemm_mma_kernel<true, false>,
                         cudaFuncAttributeMaxDynamicSharedMemorySize, SMEM_GEMM);
    cudaFuncSetAttribute(gemm_mma_kernel<false, true>,
                         cudaFuncAttributeMaxDynamicSharedMemorySize, SMEM_GEMM);

    // init via zero-memset nodes (not kernel launches)
    void *p_n64_ei, *p_n64_b, *p_deg, *p_pool, *p_sum, *p_sqs, *p_bar;
    cudaGetSymbolAddress(&p_n64_ei, g_not64_ei);
    cudaGetSymbolAddress(&p_n64_b,  g_not64_b);
    cudaGetSymbolAddress(&p_deg,    g_deg);
    cudaGetSymbolAddress(&p_pool,   g_pool);
    cudaGetSymbolAddress(&p_sum,    g_sum);
    cudaGetSymbolAddress(&p_sqs,    g_sqs);
    cudaGetSymbolAddress(&p_bar,    g_bar);
    cudaMemsetAsync(p_n64_ei, 0, 4);
    cudaMemsetAsync(p_n64_b,  0, 4);
    cudaMemsetAsync(p_bar,    0, 3 * sizeof(int));
    cudaMemsetAsync(p_deg,  0, NN * sizeof(int));
    cudaMemsetAsync(p_pool, 0, NG * NL * DD * sizeof(float));
    cudaMemsetAsync(p_sum,  0, NL * DD * sizeof(float));
    cudaMemsetAsync(p_sqs,  0, NL * DD * sizeof(float));

    preamble_kernel<<<148, 256>>>(ei32, b32, W1, W2);               // launch 0

    int zgrid = NN * DD / 4 / 256;
    int agrid = (NN * 32 + 255) / 256;

    uint32_t* wt_base;
    cudaGetSymbolAddress((void**)&wt_base, g_Wt);
    float *zb, *tb;
    cudaGetSymbolAddress((void**)&zb, g_Z);
    cudaGetSymbolAddress((void**)&tb, g_T);

    for (int l = 0; l < NL; l++) {
        agg_kernel<<<agrid, 256>>>(x, eps, l);                      // launch 1 (l=0)
        gemm_mma_kernel<true, false><<<NTILES, 256, SMEM_GEMM>>>(
            wt_base + (size_t)l * DD * AST, b1 + l * DD, zb, tb, l);      // launch 2
        gemm_mma_kernel<false, true><<<NTILES, 256, SMEM_GEMM>>>(
            wt_base + (size_t)(NL + l) * DD * AST, b2 + l * DD, tb, zb, l); // launch 3 -> ncu
        bn_relu_pool_kernel<<<zgrid, 256>>>(gamma, beta, l);
    }
    final_kernel<<<(NG * NC + 255) / 256, 256>>>(Wlin, blin, out);
}

// round 17
// speedup vs baseline: 2.1111x; 1.1051x over previous
#include <cuda_runtime.h>
#include <cstdint>

#define NN 50000
#define NE 600000
#define DD 128
#define NL 4
#define NG 512
#define NC 10
#define AST 136        // B source stride in g_Wt (floats)
#define ASTN 132       // A/T smem stride (floats); 132 mod 32 = 4 -> LDS.32 conflict-free
#define BST 40         // B chunk smem stride (floats); 40 mod 32 = 8 -> LDS.64 conflict-free
#define MT 64          // GEMM M tile
#define NTILES ((NN + MT - 1) / MT)   // 782

// ---- scratch (device globals: allocation-free) ----
__device__ float g_H[NN * DD];
__device__ float g_Z[NN * DD];
__device__ float g_sum[NL * DD];
__device__ float g_sqs[NL * DD];
__device__ float g_pool[NG * NL * DD];
__device__ uint32_t g_Wt[2][NL][DD * AST];   // transposed, pair-permuted, tf32(RNA)

__device__ int g_src[NE];
__device__ int g_dst[NE];
__device__ int g_batch[NN];
__device__ int g_deg[NN];
__device__ int g_ptr[NN + 1];
__device__ int g_off[NN];
__device__ int g_csr_src[NE];
__device__ int g_not64_ei;    // 0 = int64 source, nonzero = int32 (zero-init via memset)
__device__ int g_not64_b;
__device__ int g_bar[3];

__device__ __forceinline__ void red_add_v4(float* p, float4 v) {
    asm volatile("red.global.add.v4.f32 [%0], {%1, %2, %3, %4};"
                 :: "l"(p), "f"(v.x), "f"(v.y), "f"(v.z), "f"(v.w)
                 : "memory");
}
__device__ __forceinline__ uint32_t f2tf32(float f) {
    uint32_t u;
    asm("cvt.rna.tf32.f32 %0, %1;" : "=r"(u) : "f"(f));
    return u;
}
__device__ __forceinline__ void mma_tf32(float& c0, float& c1, float& c2, float& c3,
                                         uint32_t a0, uint32_t a1, uint32_t a2, uint32_t a3,
                                         uint32_t b0, uint32_t b1) {
    asm volatile(
        "mma.sync.aligned.m16n8k8.row.col.f32.tf32.tf32.f32 "
        "{%0,%1,%2,%3}, {%4,%5,%6,%7}, {%8,%9}, {%0,%1,%2,%3};"
        : "+f"(c0), "+f"(c1), "+f"(c2), "+f"(c3)
        : "r"(a0), "r"(a1), "r"(a2), "r"(a3), "r"(b0), "r"(b1));
}
__device__ __forceinline__ int kperm(int k) {
    return (k & ~7) + ((k & 3) << 1) + ((k >> 2) & 1);
}
__device__ __forceinline__ void cp_async16(uint32_t dst, const void* src) {
    asm volatile("cp.async.cg.shared.global [%0], [%1], 16;"
                 :: "r"(dst), "l"(src) : "memory");
}
__device__ __forceinline__ void cp_commit() {
    asm volatile("cp.async.commit_group;" ::: "memory");
}
template<int N> __device__ __forceinline__ void cp_wait() {
    asm volatile("cp.async.wait_group %0;" :: "n"(N) : "memory");
}

// ---------------- single persistent preamble kernel (148 CTAs) ----------------
__device__ __forceinline__ void gbarrier(int idx) {
    __syncthreads();
    __threadfence();
    if (threadIdx.x == 0) {
        atomicAdd(&g_bar[idx], 1);
        while (atomicAdd(&g_bar[idx], 0) < 148) __nanosleep(64);
    }
    __syncthreads();
}

__global__ __launch_bounds__(256)
void preamble_kernel(const int* __restrict__ ei32,
                     const int* __restrict__ b32,
                     const float* __restrict__ W1,
                     const float* __restrict__ W2) {
    int tid = threadIdx.x;
    const int STRIDE = 148 * 256;

    int nz_ei = 0, nz_b = 0;
    for (int i = blockIdx.x * 256 + tid; i < NE; i += STRIDE) {
        if (ei32[2 * i + 1] != 0) nz_ei = 1;
        if (2 * i + 1 < NN && b32[2 * i + 1] != 0) nz_b = 1;
    }
    int any_ei = __syncthreads_or(nz_ei);
    int any_b  = __syncthreads_or(nz_b);
    if (tid == 0) {
        if (any_ei) atomicExch(&g_not64_ei, 1);
        if (any_b)  atomicExch(&g_not64_b, 1);
    }
    gbarrier(0);

    int is64_ei = (atomicAdd(&g_not64_ei, 0) == 0);
    int is64_b  = (atomicAdd(&g_not64_b, 0) == 0);
    for (int i = blockIdx.x * 256 + tid; i < NE; i += STRIDE) {
        int s = is64_ei ? ei32[2 * i]        : ei32[i];
        int d = is64_ei ? ei32[2 * (NE + i)] : ei32[NE + i];
        g_src[i] = s;
        g_dst[i] = d;
        atomicAdd(&g_deg[d], 1);
        if (i < NN) g_batch[i] = is64_b ? b32[2 * i] : b32[i];
    }
    gbarrier(1);

    if (blockIdx.x == 0) {
        __shared__ int sh[256];
        const int CH = (NN + 255) / 256;
        int b0 = tid * CH, b1 = min(b0 + CH, NN);
        int s = 0;
        for (int i = b0; i < b1; i++) s += g_deg[i];
        sh[tid] = s;
        __syncthreads();
        #pragma unroll
        for (int off = 1; off < 256; off <<= 1) {
            int v = (tid >= off) ? sh[tid - off] : 0;
            __syncthreads();
            sh[tid] += v;
            __syncthreads();
        }
        int run = (tid > 0) ? sh[tid - 1] : 0;
        for (int i = b0; i < b1; i++) {
            g_ptr[i] = run; g_off[i] = run;
            run += g_deg[i];
        }
        if (tid == 0) g_ptr[NN] = NE;
    } else {
        for (int i = (blockIdx.x - 1) * 256 + tid; i < 2 * NL * DD * DD;
             i += 147 * 256) {
            int which = i / (NL * DD * DD);
            int r = i % (NL * DD * DD);
            int l = r / (DD * DD);
            int e = r % (DD * DD);
            int k = e / DD, n = e % DD;
            const float* w = which ? W2 : W1;
            g_Wt[which][l][n * AST + kperm(k)] = f2tf32(w[l * DD * DD + k * DD + n]);
        }
    }
    gbarrier(2);

    for (int i = blockIdx.x * 256 + tid; i < NE; i += STRIDE) {
        int d = g_dst[i];
        int pos = atomicAdd(&g_off[d], 1);
        g_csr_src[pos] = g_src[i];
    }
}

// ---------------- fused (1+eps)*h + CSR neighbor-sum (high occupancy) ----------------
__global__ void agg_kernel(const float* __restrict__ x,
                           const float* __restrict__ eps, int l) {
    int warp = (blockIdx.x * blockDim.x + threadIdx.x) >> 5;
    if (warp >= NN) return;
    int lane = threadIdx.x & 31;
    const float* h = l ? g_H : x;
    const float4* hv = (const float4*)h;
    float e = 1.0f + __ldg(&eps[l]);
    float4 a = hv[warp * 32 + lane];
    float4 acc = make_float4(a.x * e, a.y * e, a.z * e, a.w * e);
    int p = __ldg(&g_ptr[warp]);
    int p1 = __ldg(&g_ptr[warp + 1]);
    for (; p + 4 <= p1; p += 4) {
        int s0 = __ldg(&g_csr_src[p]);
        int s1 = __ldg(&g_csr_src[p + 1]);
        int s2 = __ldg(&g_csr_src[p + 2]);
        int s3 = __ldg(&g_csr_src[p + 3]);
        float4 v0 = __ldg(&hv[s0 * 32 + lane]);
        float4 v1 = __ldg(&hv[s1 * 32 + lane]);
        float4 v2 = __ldg(&hv[s2 * 32 + lane]);
        float4 v3 = __ldg(&hv[s3 * 32 + lane]);
        acc.x += v0.x + v1.x + v2.x + v3.x;
        acc.y += v0.y + v1.y + v2.y + v3.y;
        acc.z += v0.z + v1.z + v2.z + v3.z;
        acc.w += v0.w + v1.w + v2.w + v3.w;
    }
    for (; p < p1; p++) {
        int s = __ldg(&g_csr_src[p]);
        float4 v = __ldg(&hv[s * 32 + lane]);
        acc.x += v.x; acc.y += v.y; acc.z += v.z; acc.w += v.w;
    }
    ((float4*)g_Z)[warp * 32 + lane] = acc;
}

// ---------------- fused 2-GEMM MLP: Z = relu(Z@W1+b1)@W2+b2, BN stats ----------------
// Phase 1: A=Z (cp.async raw fp32) x W1 chunks -> T = relu(.+b1) stored into A smem.
// Phase 2: A=T (smem) x W2 chunks -> epilogue + stats. 3 CTAs/SM, in-place on g_Z.
#define SMEM_GEMM ((MT * ASTN + 2 * DD * BST) * 4)   // 74752 bytes

__global__ __launch_bounds__(256, 3)
void gemm_fused_kernel(const uint32_t* __restrict__ Wt1,
                       const uint32_t* __restrict__ Wt2,
                       const float* __restrict__ bias1,
                       const float* __restrict__ bias2,
                       float* __restrict__ Zio, int l) {
    extern __shared__ __align__(16) uint32_t smem[];
    uint32_t* As = smem;                       // [64][ASTN]: A (phase 1) then T (phase 2)
    uint32_t* Bs[2] = { smem + MT * ASTN, smem + MT * ASTN + DD * BST };
    int tid = threadIdx.x;
    int row0 = blockIdx.x * MT;
    int wid = tid >> 5, lane = tid & 31;
    int wm = (wid & 1) * 32;
    int wn = (wid >> 1) * 32;
    int grp = lane >> 2, qid = lane & 3;

    auto issue_a = [&](int c) {                // A k-chunk: 64 rows x 32 cols
        #pragma unroll
        for (int t = 0; t < 2; t++) {
            int idx = t * 256 + tid;
            int m = idx >> 3, j = idx & 7;
            int gm = row0 + m;
            if (gm >= NN) gm = 0;
            const float* src = Zio + (size_t)gm * DD + c * 32 + j * 4;
            uint32_t dst = (uint32_t)__cvta_generic_to_shared(As + m * ASTN + c * 32 + j * 4);
            cp_async16(dst, src);
        }
    };
    auto issue_b = [&](const uint32_t* W, int c, uint32_t* Bb) {  // B chunk: 128 x 32
        #pragma unroll
        for (int t = 0; t < 4; t++) {
            int idx = t * 256 + tid;
            int r = idx >> 3, j = idx & 7;
            const uint32_t* src = W + r * AST + c * 32 + j * 4;
            uint32_t dst = (uint32_t)__cvta_generic_to_shared(Bb + r * BST + j * 4);
            cp_async16(dst, src);
        }
    };

    // phase 1 prologue: groups (A0+W1_0), (A1+W1_1)
    issue_a(0); issue_b(Wt1, 0, Bs[0]); cp_commit();
    issue_a(1); issue_b(Wt1, 1, Bs[1]); cp_commit();

    const uint32_t* A0p = &As[(wm + grp) * ASTN];
    const uint32_t* A1p = A0p + 8 * ASTN;
    const uint32_t* A2p = A0p + 16 * ASTN;
    const uint32_t* A3p = A0p + 24 * ASTN;

    float acc[2][4][4];
    #pragma unroll
    for (int i = 0; i < 2; i++)
        #pragma unroll
        for (int j = 0; j < 4; j++)
            #pragma unroll
            for (int q = 0; q < 4; q++) acc[i][j][q] = 0.f;

    // -------- phase 1 mainloop --------
    #pragma unroll
    for (int c = 0; c < 4; c++) {
        if (c < 3) cp_wait<1>(); else cp_wait<0>();
        __syncthreads();
        const uint32_t* Brow = &Bs[c & 1][(wn + grp) * BST + qid * 2];
        #pragma unroll
        for (int j = 0; j < 4; j++) {
            int ka = c * 32 + j * 8 + qid;
            uint32_t a0 = A0p[ka], a0h = A0p[ka + 4];
            uint32_t a1 = A1p[ka], a1h = A1p[ka + 4];
            uint32_t a2 = A2p[ka], a2h = A2p[ka + 4];
            uint32_t a3 = A3p[ka], a3h = A3p[ka + 4];
            #pragma unroll
            for (int nt = 0; nt < 4; nt++) {
                uint2 b = *(const uint2*)(Brow + nt * 8 * BST + j * 8);
                mma_tf32(acc[0][nt][0], acc[0][nt][1], acc[0][nt][2], acc[0][nt][3],
                         a0, a1, a0h, a1h, b.x, b.y);
                mma_tf32(acc[1][nt][0], acc[1][nt][1], acc[1][nt][2], acc[1][nt][3],
                         a2, a3, a2h, a3h, b.x, b.y);
            }
        }
        if (c < 2) {
            __syncthreads();
            issue_a(c + 2); issue_b(Wt1, c + 2, Bs[c & 1]); cp_commit();
        }
    }
    __syncthreads();                           // all reads of As/Bs complete

    // prefetch W2 chunks 0,1 while T is stored
    issue_b(Wt2, 0, Bs[0]); cp_commit();
    issue_b(Wt2, 1, Bs[1]); cp_commit();

    // T = relu(acc + b1) -> As (overwrite A tile)
    float* Tf = (float*)As;
    #pragma unroll
    for (int nt = 0; nt < 4; nt++) {
        int col = wn + nt * 8 + 2 * qid;
        float bv0 = __ldg(&bias1[col]);
        float bv1 = __ldg(&bias1[col + 1]);
        #pragma unroll
        for (int mt = 0; mt < 2; mt++) {
            int rl = wm + mt * 16 + grp;
            float v0 = fmaxf(acc[mt][nt][0] + bv0, 0.f);
            float v1 = fmaxf(acc[mt][nt][1] + bv1, 0.f);
            float v2 = fmaxf(acc[mt][nt][2] + bv0, 0.f);
            float v3 = fmaxf(acc[mt][nt][3] + bv1, 0.f);
            *(float2*)(Tf + rl * ASTN + col) = make_float2(v0, v1);
            *(float2*)(Tf + (rl + 8) * ASTN + col) = make_float2(v2, v3);
        }
    }

    #pragma unroll
    for (int i = 0; i < 2; i++)
        #pragma unroll
        for (int j = 0; j < 4; j++)
            #pragma unroll
            for (int q = 0; q < 4; q++) acc[i][j][q] = 0.f;

    // -------- phase 2 mainloop (A = T in smem) --------
    #pragma unroll
    for (int c = 0; c < 4; c++) {
        if (c < 3) cp_wait<1>(); else cp_wait<0>();
        __syncthreads();                       // covers T stores on c==0
        const uint32_t* Brow = &Bs[c & 1][(wn + grp) * BST + qid * 2];
        #pragma unroll
        for (int j = 0; j < 4; j++) {
            int ka = c * 32 + j * 8 + qid;
            uint32_t a0 = A0p[ka], a0h = A0p[ka + 4];
            uint32_t a1 = A1p[ka], a1h = A1p[ka + 4];
            uint32_t a2 = A2p[ka], a2h = A2p[ka + 4];
            uint32_t a3 = A3p[ka], a3h = A3p[ka + 4];
            #pragma unroll
            for (int nt = 0; nt < 4; nt++) {
                uint2 b = *(const uint2*)(Brow + nt * 8 * BST + j * 8);
                mma_tf32(acc[0][nt][0], acc[0][nt][1], acc[0][nt][2], acc[0][nt][3],
                         a0, a1, a0h, a1h, b.x, b.y);
                mma_tf32(acc[1][nt][0], acc[1][nt][1], acc[1][nt][2], acc[1][nt][3],
                         a2, a3, a2h, a3h, b.x, b.y);
            }
        }
        if (c < 2) {
            __syncthreads();
            issue_b(Wt2, c + 2, Bs[c & 1]); cp_commit();
        }
    }

    // epilogue: Z = acc + b2, store + BN stats
    #pragma unroll
    for (int nt = 0; nt < 4; nt++) {
        int col = wn + nt * 8 + 2 * qid;
        float bv0 = __ldg(&bias2[col]);
        float bv1 = __ldg(&bias2[col + 1]);
        float s0 = 0.f, s1 = 0.f, q0 = 0.f, q1 = 0.f;
        #pragma unroll
        for (int mt = 0; mt < 2; mt++) {
            int r = row0 + wm + mt * 16 + grp;
            float v0 = acc[mt][nt][0] + bv0;
            float v1 = acc[mt][nt][1] + bv1;
            float v2 = acc[mt][nt][2] + bv0;
            float v3 = acc[mt][nt][3] + bv1;
            if (r < NN) {
                *(float2*)(Zio + (size_t)r * DD + col) = make_float2(v0, v1);
                s0 += v0; s1 += v1; q0 += v0 * v0; q1 += v1 * v1;
            }
            if (r + 8 < NN) {
                *(float2*)(Zio + (size_t)(r + 8) * DD + col) = make_float2(v2, v3);
                s0 += v2; s1 += v3; q0 += v2 * v2; q1 += v3 * v3;
            }
        }
        #pragma unroll
        for (int m = 4; m < 32; m <<= 1) {
            s0 += __shfl_xor_sync(0xFFFFFFFF, s0, m);
            s1 += __shfl_xor_sync(0xFFFFFFFF, s1, m);
            q0 += __shfl_xor_sync(0xFFFFFFFF, q0, m);
            q1 += __shfl_xor_sync(0xFFFFFFFF, q1, m);
        }
        if (grp == 0) {
            atomicAdd(&g_sum[l * DD + col], s0);
            atomicAdd(&g_sum[l * DD + col + 1], s1);
            atomicAdd(&g_sqs[l * DD + col], q0);
            atomicAdd(&g_sqs[l * DD + col + 1], q1);
        }
    }
}

// ---------------- BN finalize + relu + pool (block-local pooling) ----------------
__global__ void bn_relu_pool_kernel(const float* __restrict__ gamma,
                                    const float* __restrict__ beta, int l) {
    __shared__ float s_sc[DD], s_sf[DD];
    __shared__ float4 buf[256];
    int tid = threadIdx.x;
    if (tid < DD) {
        float mean = g_sum[l * DD + tid] * (1.0f / NN);
        float var = g_sqs[l * DD + tid] * (1.0f / NN) - mean * mean;
        float sc = __ldg(&gamma[l * DD + tid]) * rsqrtf(var + 1e-5f);
        s_sc[tid] = sc;
        s_sf[tid] = __ldg(&beta[l * DD + tid]) - mean * sc;
    }
    __syncthreads();
    int i = blockIdx.x * 256 + tid;
    int r = i >> 5;
    int c4 = (i & 31) << 2;
    float4 z = ((const float4*)g_Z)[i];
    float4 hv;
    hv.x = fmaxf(z.x * s_sc[c4]     + s_sf[c4],     0.f);
    hv.y = fmaxf(z.y * s_sc[c4 + 1] + s_sf[c4 + 1], 0.f);
    hv.z = fmaxf(z.z * s_sc[c4 + 2] + s_sf[c4 + 2], 0.f);
    hv.w = fmaxf(z.w * s_sc[c4 + 3] + s_sf[c4 + 3], 0.f);
    ((float4*)g_H)[i] = hv;

    int r0 = (blockIdx.x * 256) >> 5;
    int bfirst = __ldg(&g_batch[r0]);
    int blast  = __ldg(&g_batch[r0 + 7]);
    if (bfirst == blast) {
        buf[tid] = hv;
        __syncthreads();
        if (tid < 128) {
            buf[tid].x += buf[tid + 128].x; buf[tid].y += buf[tid + 128].y;
            buf[tid].z += buf[tid + 128].z; buf[tid].w += buf[tid + 128].w;
        }
        __syncthreads();
        if (tid < 64) {
            buf[tid].x += buf[tid + 64].x; buf[tid].y += buf[tid + 64].y;
            buf[tid].z += buf[tid + 64].z; buf[tid].w += buf[tid + 64].w;
        }
        __syncthreads();
        if (tid < 32) {
            float4 v = buf[tid];
            float4 w = buf[tid + 32];
            v.x += w.x; v.y += w.y; v.z += w.z; v.w += w.w;
            red_add_v4(&g_pool[(size_t)bfirst * (NL * DD) + l * DD + (tid << 2)], v);
        }
    } else {
        int b = __ldg(&g_batch[r]);
        red_add_v4(&g_pool[(size_t)b * (NL * DD) + l * DD + c4], hv);
    }
}

// ---------------- final linear ----------------
__global__ void final_kernel(const float* __restrict__ Wlin,
                             const float* __restrict__ blin,
                             float* __restrict__ out) {
    int t = blockIdx.x * blockDim.x + threadIdx.x;
    if (t >= NG * NC) return;
    int gph = t / NC, c = t % NC;
    float acc = __ldg(&blin[c]);
    const float* prow = &g_pool[(size_t)gph * (NL * DD)];
    #pragma unroll 8
    for (int k = 0; k < NL * DD; k++)
        acc += __ldg(&prow[k]) * __ldg(&Wlin[k * NC + c]);
    out[gph * NC + c] = acc;
}

extern "C" void kernel_launch(void* const* d_in, const int* in_sizes, int n_in,
                              void* d_out, int out_size) {
    const float* x     = (const float*)d_in[0];
    const int*   ei32  = (const int*)d_in[1];
    const int*   b32   = (const int*)d_in[2];
    const float* W1    = (const float*)d_in[3];
    const float* b1    = (const float*)d_in[4];
    const float* W2    = (const float*)d_in[5];
    const float* b2    = (const float*)d_in[6];
    const float* eps   = (const float*)d_in[7];
    const float* gamma = (const float*)d_in[8];
    const float* beta  = (const float*)d_in[9];
    const float* Wlin  = (const float*)d_in[10];
    const float* blin  = (const float*)d_in[11];
    float* out = (float*)d_out;

    cudaFuncSetAttribute(gemm_fused_kernel,
                         cudaFuncAttributeMaxDynamicSharedMemorySize, SMEM_GEMM);

    // init via zero-memset nodes (not kernel launches)
    void *p_n64_ei, *p_n64_b, *p_deg, *p_pool, *p_sum, *p_sqs, *p_bar;
    cudaGetSymbolAddress(&p_n64_ei, g_not64_ei);
    cudaGetSymbolAddress(&p_n64_b,  g_not64_b);
    cudaGetSymbolAddress(&p_deg,    g_deg);
    cudaGetSymbolAddress(&p_pool,   g_pool);
    cudaGetSymbolAddress(&p_sum,    g_sum);
    cudaGetSymbolAddress(&p_sqs,    g_sqs);
    cudaGetSymbolAddress(&p_bar,    g_bar);
    cudaMemsetAsync(p_n64_ei, 0, 4);
    cudaMemsetAsync(p_n64_b,  0, 4);
    cudaMemsetAsync(p_bar,    0, 3 * sizeof(int));
    cudaMemsetAsync(p_deg,  0, NN * sizeof(int));
    cudaMemsetAsync(p_pool, 0, NG * NL * DD * sizeof(float));
    cudaMemsetAsync(p_sum,  0, NL * DD * sizeof(float));
    cudaMemsetAsync(p_sqs,  0, NL * DD * sizeof(float));

    preamble_kernel<<<148, 256>>>(ei32, b32, W1, W2);               // launch 0

    int zgrid = NN * DD / 4 / 256;
    int agrid = (NN * 32 + 255) / 256;

    uint32_t* wt_base;
    cudaGetSymbolAddress((void**)&wt_base, g_Wt);
    float* zb;
    cudaGetSymbolAddress((void**)&zb, g_Z);

    for (int l = 0; l < NL; l++) {
        agg_kernel<<<agrid, 256>>>(x, eps, l);                      // launch 1 (l=0)
        gemm_fused_kernel<<<NTILES, 256, SMEM_GEMM>>>(
            wt_base + (size_t)l * DD * AST,
            wt_base + (size_t)(NL + l) * DD * AST,
            b1 + l * DD, b2 + l * DD, zb, l);                       // launch 2 (l=0)
        bn_relu_pool_kernel<<<zgrid, 256>>>(gamma, beta, l);        // launch 3 (l=0)
    }
    final_kernel<<<(NG * NC + 255) / 256, 256>>>(Wlin, blin, out);
}